// round 11
// baseline (speedup 1.0000x reference)
#include <cuda_runtime.h>
#include <math.h>
#include <stdint.h>

// ---------------------------------------------------------------------------
// Shapes (fixed by the problem)
// ---------------------------------------------------------------------------
#define B    32
#define L    65536
#define LOUT 64536          // L - 1000 (slice [500:-500])

// Scratch (device globals; allocation in kernel_launch is forbidden)
__device__ float g_y[(size_t)B * 40 * L];   // motif output (post-softplus)
__device__ float g_s[(size_t)B * 4 * L];    // reduce output
__device__ float g_t[(size_t)B * 4 * L];    // fftconv output
__device__ float g_m[(size_t)B * 40 * L];   // motifact (gated)

// ---------------------------------------------------------------------------
// tf32 MMA helpers (shared)
// ---------------------------------------------------------------------------
__device__ __forceinline__ uint32_t f2tf(float v) {
    uint32_t r;
    asm("cvt.rna.tf32.f32 %0, %1;" : "=r"(r) : "f"(v));
    return r;
}

__device__ __forceinline__ void mma_tf32(float& d0, float& d1, float& d2, float& d3,
                                         uint32_t a0, uint32_t a1, uint32_t a2, uint32_t a3,
                                         uint32_t b0, uint32_t b1) {
    asm volatile(
        "mma.sync.aligned.m16n8k8.row.col.f32.tf32.tf32.f32 "
        "{%0,%1,%2,%3}, {%4,%5,%6,%7}, {%8,%9}, {%0,%1,%2,%3};\n"
        : "+f"(d0), "+f"(d1), "+f"(d2), "+f"(d3)
        : "r"(a0), "r"(a1), "r"(a2), "r"(a3), "r"(b0), "r"(b1));
}

// ---------------------------------------------------------------------------
// Kernel 1: motif conv (4->40, K=51, pad 25) + softplus + reduce (40->4, 1x1)
//   (proven scalar version — frozen)
// ---------------------------------------------------------------------------
#define T1   512
#define TH1  128
#define K1P  52
#define XW1  564

__global__ __launch_bounds__(TH1)
void motif_kernel(const float* __restrict__ x,
                  const float* __restrict__ wm, const float* __restrict__ bm,
                  const float* __restrict__ wr, const float* __restrict__ br)
{
    __shared__ __align__(16) float swm[4 * K1P * 40];
    __shared__ float swr[4 * 40];
    __shared__ float sbm[40];
    __shared__ float sbr[4];
    __shared__ __align__(16) float sx[4 * XW1];

    const int b   = blockIdx.y;
    const int l0  = blockIdx.x * T1;
    const int tid = threadIdx.x;

    for (int i = tid; i < 4 * K1P * 40; i += TH1) {
        int c  = i / (K1P * 40);
        int r  = i - c * (K1P * 40);
        int k  = r / 40;
        int oc = r - k * 40;
        swm[i] = (k < 51) ? wm[(oc * 4 + c) * 51 + k] : 0.f;
    }
    for (int i = tid; i < 160; i += TH1) swr[i] = wr[i];
    if (tid < 40) sbm[tid] = bm[tid];
    if (tid < 4)  sbr[tid] = br[tid];

    for (int i = tid; i < 4 * XW1; i += TH1) {
        int c   = i / XW1;
        int off = i - c * XW1;
        int g   = l0 - 25 + off;
        sx[i]   = (g >= 0 && g < L) ? x[(b * 4 + c) * L + g] : 0.f;
    }
    __syncthreads();

    const int tp = tid * 4;

    float sacc[4][4];
#pragma unroll
    for (int rc = 0; rc < 4; rc++) {
        float bv = sbr[rc];
#pragma unroll
        for (int j = 0; j < 4; j++) sacc[rc][j] = bv;
    }

    for (int ocg = 0; ocg < 40; ocg += 8) {
        float acc[8][4];
#pragma unroll
        for (int o = 0; o < 8; o++) {
            float bv = sbm[ocg + o];
#pragma unroll
            for (int j = 0; j < 4; j++) acc[o][j] = bv;
        }

#pragma unroll
        for (int c = 0; c < 4; c++) {
            const float* xb = &sx[c * XW1 + tp];
            const float* wb = &swm[c * (K1P * 40) + ocg];
#pragma unroll 1
            for (int kg = 0; kg < K1P / 4; kg++) {
                const int k0 = kg * 4;
                float xq[8];
                float4 xa = *(const float4*)(xb + k0);
                float4 xc = *(const float4*)(xb + k0 + 4);
                xq[0]=xa.x; xq[1]=xa.y; xq[2]=xa.z; xq[3]=xa.w;
                xq[4]=xc.x; xq[5]=xc.y; xq[6]=xc.z; xq[7]=xc.w;
#pragma unroll
                for (int kk = 0; kk < 4; kk++) {
                    float4 wa = *(const float4*)(wb + (k0 + kk) * 40);
                    float4 wc = *(const float4*)(wb + (k0 + kk) * 40 + 4);
                    float wv[8] = {wa.x, wa.y, wa.z, wa.w, wc.x, wc.y, wc.z, wc.w};
#pragma unroll
                    for (int j = 0; j < 4; j++) {
                        float xv = xq[kk + j];
#pragma unroll
                        for (int o = 0; o < 8; o++)
                            acc[o][j] = fmaf(wv[o], xv, acc[o][j]);
                    }
                }
            }
        }

#pragma unroll
        for (int o = 0; o < 8; o++) {
            const int oc = ocg + o;
            float4 yv;
            float* yp = (float*)&yv;
#pragma unroll
            for (int j = 0; j < 4; j++) {
                float v  = acc[o][j];
                float sp = fmaxf(v, 0.f) + __logf(1.f + __expf(-fabsf(v)));
                yp[j] = sp;
#pragma unroll
                for (int rc = 0; rc < 4; rc++)
                    sacc[rc][j] = fmaf(swr[rc * 40 + oc], sp, sacc[rc][j]);
            }
            *(float4*)&g_y[(size_t)(b * 40 + oc) * L + l0 + tp] = yv;
        }
    }

#pragma unroll
    for (int rc = 0; rc < 4; rc++) {
        float4 sv = make_float4(sacc[rc][0], sacc[rc][1], sacc[rc][2], sacc[rc][3]);
        *(float4*)&g_s[(size_t)(b * 4 + rc) * L + l0 + tp] = sv;
    }
}

// ---------------------------------------------------------------------------
// Kernel 2: fftconv (4->4, K=401, pad 200) via tf32 mma  (R10 proven — frozen)
// ---------------------------------------------------------------------------
#define FT_POS   1024
#define FT_TH    128
#define FT_NT    8
#define FT_NJ    432
#define FT_WOFF  24
#define FT_WPAD  464
#define FT_XW    1472

__global__ __launch_bounds__(FT_TH)
void fftconv_kernel(const float* __restrict__ wf, const float* __restrict__ bf)
{
    __shared__ __align__(16) uint2 sx[FT_XW];
    __shared__ __align__(16) uint2 sw[4 * FT_WPAD];

    const int b    = blockIdx.y;
    const int TO0  = blockIdx.x * FT_POS;
    const int tid  = threadIdx.x;
    const int wid  = tid >> 5;
    const int lane = tid & 31;
    const int grp  = lane >> 2;
    const int tig  = lane & 3;
    const int wrel = wid * (FT_NT * 32);

    const int oc_lo = grp >> 2;
    const int oc_hi = oc_lo + 2;
    const int mp    = grp & 3;

    float acc[FT_NT][4];
    {
        float blo = bf[oc_lo], bhi = bf[oc_hi];
#pragma unroll
        for (int t = 0; t < FT_NT; t++) {
            acc[t][0] = blo; acc[t][1] = blo;
            acc[t][2] = bhi; acc[t][3] = bhi;
        }
    }

#pragma unroll 1
    for (int c = 0; c < 4; c++) {
        __syncthreads();
        for (int i = tid; i < 4 * FT_WPAD; i += FT_TH) {
            int oc = i / FT_WPAD;
            int r  = i - oc * FT_WPAD;
            int k0 = r - FT_WOFF;
            int k1 = k0 + 4;
            float v0 = (k0 >= 0 && k0 < 401) ? wf[(oc * 4 + c) * 401 + k0] : 0.f;
            float v1 = (k1 >= 0 && k1 < 401) ? wf[(oc * 4 + c) * 401 + k1] : 0.f;
            sw[i] = make_uint2(f2tf(v0), f2tf(v1));
        }
        {
            const float* sp = &g_s[(size_t)(b * 4 + c) * L];
            for (int i = tid; i < FT_XW; i += FT_TH) {
                int g  = TO0 - 200 + i;
                int g4 = g + 4;
                float v0 = (g  >= 0 && g  < L) ? sp[g]  : 0.f;
                float v1 = (g4 >= 0 && g4 < L) ? sp[g4] : 0.f;
                sx[i] = make_uint2(f2tf(v0), f2tf(v1));
            }
        }
        __syncthreads();

        const uint2* xw  = &sx[wrel];
        const uint2* wlo = &sw[oc_lo * FT_WPAD];
        const uint2* whi = &sw[oc_hi * FT_WPAD];
        int ai = FT_WOFF + tig - 8 * mp;
        int bi = grp + tig;
#pragma unroll 1
        for (int J0 = 0; J0 < FT_NJ; J0 += 8) {
            uint2 aLo = wlo[ai];
            uint2 aHi = whi[ai];
#pragma unroll
            for (int t = 0; t < FT_NT; t++) {
                uint2 bb = xw[bi + t * 32];
                mma_tf32(acc[t][0], acc[t][1], acc[t][2], acc[t][3],
                         aLo.x, aHi.x, aLo.y, aHi.y, bb.x, bb.y);
            }
            ai += 8; bi += 8;
        }
    }

    float* tlo = &g_t[(size_t)(b * 4 + oc_lo) * L];
    float* thi = &g_t[(size_t)(b * 4 + oc_hi) * L];
#pragma unroll
    for (int t = 0; t < FT_NT; t++) {
        int pos = TO0 + wrel + t * 32 + 8 * mp + 2 * tig;
        *(float2*)&tlo[pos] = make_float2(acc[t][0], acc[t][1]);
        *(float2*)&thi[pos] = make_float2(acc[t][2], acc[t][3]);
    }
}

// ---------------------------------------------------------------------------
// Kernel 3: expand (4->40, 1x1) + sigmoid gate * y  -> motifact  (frozen)
// ---------------------------------------------------------------------------
__global__ __launch_bounds__(256)
void gate_kernel(const float* __restrict__ we, const float* __restrict__ be)
{
    __shared__ float sw[160];
    __shared__ float sb[40];
    const int tid = threadIdx.x;
    if (tid < 160) sw[tid] = we[tid];
    if (tid < 40)  sb[tid] = be[tid];
    __syncthreads();

    const int b = blockIdx.y;
    const int l = (blockIdx.x * 256 + tid) * 4;

    float4 tv[4];
#pragma unroll
    for (int rc = 0; rc < 4; rc++)
        tv[rc] = *(const float4*)&g_t[(size_t)(b * 4 + rc) * L + l];

    for (int oc = 0; oc < 40; oc++) {
        float w0 = sw[oc * 4 + 0], w1 = sw[oc * 4 + 1];
        float w2 = sw[oc * 4 + 2], w3 = sw[oc * 4 + 3];
        float bb = sb[oc];
        float4 g;
        g.x = bb + w0 * tv[0].x + w1 * tv[1].x + w2 * tv[2].x + w3 * tv[3].x;
        g.y = bb + w0 * tv[0].y + w1 * tv[1].y + w2 * tv[2].y + w3 * tv[3].y;
        g.z = bb + w0 * tv[0].z + w1 * tv[1].z + w2 * tv[2].z + w3 * tv[3].z;
        g.w = bb + w0 * tv[0].w + w1 * tv[1].w + w2 * tv[2].w + w3 * tv[3].w;
        g.x = 1.f / (1.f + __expf(-g.x));
        g.y = 1.f / (1.f + __expf(-g.y));
        g.z = 1.f / (1.f + __expf(-g.z));
        g.w = 1.f / (1.f + __expf(-g.w));
        size_t idx = (size_t)(b * 40 + oc) * L + l;
        float4 yv = *(const float4*)&g_y[idx];
        float4 mv = make_float4(g.x * yv.x, g.y * yv.y, g.z * yv.z, g.w * yv.w);
        *(float4*)&g_m[idx] = mv;
    }
}

// ---------------------------------------------------------------------------
// Kernel 4: effect conv (40->2, K=601) via tf32 mma — R8 shape + uint2-paired
//   smem operands (halves LDS instructions and wavefronts), 1 ch per chunk.
//   sm_x[i] = {tf32(x[g]), tf32(x[g+4])};  sm_w[oc][i] = {tf32(w[k]), tf32(w[k+4])}
//   A frag = 2 x LDS.64 per oc; B frag = 1 x LDS.64 per tile.
// ---------------------------------------------------------------------------
#define ET_POS   2048       // positions per CTA
#define ET_TH    128
#define ET_WLEN  2656       // uint2 x-window entries
#define ET_WPAD  864        // uint2 weight entries per oc (band at offset 128)
#define ET_NJ    728        // extended j range (91 chunks of 8)

__global__ __launch_bounds__(ET_TH)
void effect_kernel(const float* __restrict__ w, const float* __restrict__ bias,
                   float* __restrict__ out)
{
    __shared__ __align__(16) uint2 sm_x[ET_WLEN];      // {x[i], x[i+4]}
    __shared__ __align__(16) uint2 sm_w[2 * ET_WPAD];  // [oc][{w[k], w[k+4]}]

    const int b    = blockIdx.y;
    const int LOc  = blockIdx.x * ET_POS;
    const int tid  = threadIdx.x;
    const int wid  = tid >> 5;
    const int lane = tid & 31;
    const int grp  = lane >> 2;
    const int tig  = lane & 3;
    const int wrel = wid * 512;

    float acc[4][2][4];
    const float b0v = bias[0], b1v = bias[1];
#pragma unroll
    for (int t = 0; t < 4; t++)
#pragma unroll
        for (int r = 0; r < 4; r++) { acc[t][0][r] = b0v; acc[t][1][r] = b1v; }

#pragma unroll 1
    for (int ch = 0; ch < 40; ch++) {
        __syncthreads();   // protect previous chunk's smem
        // weights: band at offset 128, pair {w[k], w[k+4]}, zero-guarded
        for (int i = tid; i < 2 * ET_WPAD; i += ET_TH) {
            int oc = i / ET_WPAD;
            int r  = i - oc * ET_WPAD;
            int k0 = r - 128;
            int k1 = k0 + 4;
            const float* wp = &w[((size_t)(oc * 40 + ch)) * 601];
            float v0 = (k0 >= 0 && k0 < 601) ? wp[k0] : 0.f;
            float v1 = (k1 >= 0 && k1 < 601) ? wp[k1] : 0.f;
            sm_w[i] = make_uint2(f2tf(v0), f2tf(v1));
        }
        // x window: {x[g], x[g+4]}, g = LOc + 200 + i (always >= 0)
        {
            const float* xm = &g_m[(size_t)(b * 40 + ch) * L];
            for (int i = tid; i < ET_WLEN; i += ET_TH) {
                int g  = LOc + 200 + i;
                float v0 = (g < L)     ? xm[g]     : 0.f;
                float v1 = (g + 4 < L) ? xm[g + 4] : 0.f;
                sm_x[i] = make_uint2(f2tf(v0), f2tf(v1));
            }
        }
        __syncthreads();

        const uint2* xw  = &sm_x[wrel];
        const uint2* w0p = &sm_w[0];
        const uint2* w1p = &sm_w[ET_WPAD];
        int ai = 128 + tig - 8 * grp;   // + J0 each step
        int bi = grp + tig;             // + J0 each step (+ t*128)
#pragma unroll 1
        for (int J0 = 0; J0 < ET_NJ; J0 += 8) {
            uint2 a0  = w0p[ai];        // (a00, a02)
            uint2 a0m = w0p[ai - 64];   // (a01, a03)
            uint2 a1  = w1p[ai];
            uint2 a1m = w1p[ai - 64];
#pragma unroll
            for (int t = 0; t < 4; t++) {
                uint2 bb = xw[bi + t * 128];
                mma_tf32(acc[t][0][0], acc[t][0][1], acc[t][0][2], acc[t][0][3],
                         a0.x, a0m.x, a0.y, a0m.y, bb.x, bb.y);
                mma_tf32(acc[t][1][0], acc[t][1][1], acc[t][1][2], acc[t][1][3],
                         a1.x, a1m.x, a1.y, a1m.y, bb.x, bb.y);
            }
            ai += 8; bi += 8;
        }
    }

    // epilogue: sigmoid + store
#pragma unroll
    for (int t = 0; t < 4; t++) {
        int base = LOc + wrel + t * 128;
        int p0   = base + 8 * grp + 2 * tig;
        int p2   = p0 + 64;
#pragma unroll
        for (int oc = 0; oc < 2; oc++) {
            float* op = out + (size_t)(b * 2 + oc) * LOUT;
            float s0 = 1.f / (1.f + __expf(-acc[t][oc][0]));
            float s1 = 1.f / (1.f + __expf(-acc[t][oc][1]));
            float s2 = 1.f / (1.f + __expf(-acc[t][oc][2]));
            float s3 = 1.f / (1.f + __expf(-acc[t][oc][3]));
            if (p0 < LOUT)     op[p0]     = s0;
            if (p0 + 1 < LOUT) op[p0 + 1] = s1;
            if (p2 < LOUT)     op[p2]     = s2;
            if (p2 + 1 < LOUT) op[p2 + 1] = s3;
        }
    }
}

// ---------------------------------------------------------------------------
// Launch
// ---------------------------------------------------------------------------
extern "C" void kernel_launch(void* const* d_in, const int* in_sizes, int n_in,
                              void* d_out, int out_size)
{
    const float* x   = (const float*)d_in[0];
    const float* wm  = (const float*)d_in[1];
    const float* bm  = (const float*)d_in[2];
    const float* wr  = (const float*)d_in[3];
    const float* br  = (const float*)d_in[4];
    const float* wf  = (const float*)d_in[5];
    const float* bf  = (const float*)d_in[6];
    const float* wex = (const float*)d_in[7];
    const float* bex = (const float*)d_in[8];
    const float* wef = (const float*)d_in[9];
    const float* bef = (const float*)d_in[10];
    float* out = (float*)d_out;

    motif_kernel  <<<dim3(L / T1, B), TH1>>>(x, wm, bm, wr, br);
    fftconv_kernel<<<dim3(L / FT_POS, B), FT_TH>>>(wf, bf);
    gate_kernel   <<<dim3(L / 1024, B), 256>>>(wex, bex);
    effect_kernel <<<dim3((LOUT + ET_POS - 1) / ET_POS, B), ET_TH>>>(wef, bef, out);
}

// round 12
// speedup vs baseline: 1.1348x; 1.1348x over previous
#include <cuda_runtime.h>
#include <math.h>
#include <stdint.h>

// ---------------------------------------------------------------------------
// Shapes (fixed by the problem)
// ---------------------------------------------------------------------------
#define B    32
#define L    65536
#define LOUT 64536          // L - 1000 (slice [500:-500])

// Scratch (device globals; allocation in kernel_launch is forbidden)
__device__ float g_y[(size_t)B * 40 * L];   // motif output (post-softplus)
__device__ float g_s[(size_t)B * 4 * L];    // reduce output
__device__ float g_t[(size_t)B * 4 * L];    // fftconv output
__device__ float g_m[(size_t)B * 40 * L];   // motifact (gated)

// ---------------------------------------------------------------------------
// tf32 MMA helpers (shared)
// ---------------------------------------------------------------------------
__device__ __forceinline__ uint32_t f2tf(float v) {
    uint32_t r;
    asm("cvt.rna.tf32.f32 %0, %1;" : "=r"(r) : "f"(v));
    return r;
}

__device__ __forceinline__ void mma_tf32(float& d0, float& d1, float& d2, float& d3,
                                         uint32_t a0, uint32_t a1, uint32_t a2, uint32_t a3,
                                         uint32_t b0, uint32_t b1) {
    asm volatile(
        "mma.sync.aligned.m16n8k8.row.col.f32.tf32.tf32.f32 "
        "{%0,%1,%2,%3}, {%4,%5,%6,%7}, {%8,%9}, {%0,%1,%2,%3};\n"
        : "+f"(d0), "+f"(d1), "+f"(d2), "+f"(d3)
        : "r"(a0), "r"(a1), "r"(a2), "r"(a3), "r"(b0), "r"(b1));
}

// ---------------------------------------------------------------------------
// Kernel 1: motif conv (4->40, K=51, pad 25) + softplus + reduce (40->4, 1x1)
//   (proven scalar version — frozen)
// ---------------------------------------------------------------------------
#define T1   512
#define TH1  128
#define K1P  52
#define XW1  564

__global__ __launch_bounds__(TH1)
void motif_kernel(const float* __restrict__ x,
                  const float* __restrict__ wm, const float* __restrict__ bm,
                  const float* __restrict__ wr, const float* __restrict__ br)
{
    __shared__ __align__(16) float swm[4 * K1P * 40];
    __shared__ float swr[4 * 40];
    __shared__ float sbm[40];
    __shared__ float sbr[4];
    __shared__ __align__(16) float sx[4 * XW1];

    const int b   = blockIdx.y;
    const int l0  = blockIdx.x * T1;
    const int tid = threadIdx.x;

    for (int i = tid; i < 4 * K1P * 40; i += TH1) {
        int c  = i / (K1P * 40);
        int r  = i - c * (K1P * 40);
        int k  = r / 40;
        int oc = r - k * 40;
        swm[i] = (k < 51) ? wm[(oc * 4 + c) * 51 + k] : 0.f;
    }
    for (int i = tid; i < 160; i += TH1) swr[i] = wr[i];
    if (tid < 40) sbm[tid] = bm[tid];
    if (tid < 4)  sbr[tid] = br[tid];

    for (int i = tid; i < 4 * XW1; i += TH1) {
        int c   = i / XW1;
        int off = i - c * XW1;
        int g   = l0 - 25 + off;
        sx[i]   = (g >= 0 && g < L) ? x[(b * 4 + c) * L + g] : 0.f;
    }
    __syncthreads();

    const int tp = tid * 4;

    float sacc[4][4];
#pragma unroll
    for (int rc = 0; rc < 4; rc++) {
        float bv = sbr[rc];
#pragma unroll
        for (int j = 0; j < 4; j++) sacc[rc][j] = bv;
    }

    for (int ocg = 0; ocg < 40; ocg += 8) {
        float acc[8][4];
#pragma unroll
        for (int o = 0; o < 8; o++) {
            float bv = sbm[ocg + o];
#pragma unroll
            for (int j = 0; j < 4; j++) acc[o][j] = bv;
        }

#pragma unroll
        for (int c = 0; c < 4; c++) {
            const float* xb = &sx[c * XW1 + tp];
            const float* wb = &swm[c * (K1P * 40) + ocg];
#pragma unroll 1
            for (int kg = 0; kg < K1P / 4; kg++) {
                const int k0 = kg * 4;
                float xq[8];
                float4 xa = *(const float4*)(xb + k0);
                float4 xc = *(const float4*)(xb + k0 + 4);
                xq[0]=xa.x; xq[1]=xa.y; xq[2]=xa.z; xq[3]=xa.w;
                xq[4]=xc.x; xq[5]=xc.y; xq[6]=xc.z; xq[7]=xc.w;
#pragma unroll
                for (int kk = 0; kk < 4; kk++) {
                    float4 wa = *(const float4*)(wb + (k0 + kk) * 40);
                    float4 wc = *(const float4*)(wb + (k0 + kk) * 40 + 4);
                    float wv[8] = {wa.x, wa.y, wa.z, wa.w, wc.x, wc.y, wc.z, wc.w};
#pragma unroll
                    for (int j = 0; j < 4; j++) {
                        float xv = xq[kk + j];
#pragma unroll
                        for (int o = 0; o < 8; o++)
                            acc[o][j] = fmaf(wv[o], xv, acc[o][j]);
                    }
                }
            }
        }

#pragma unroll
        for (int o = 0; o < 8; o++) {
            const int oc = ocg + o;
            float4 yv;
            float* yp = (float*)&yv;
#pragma unroll
            for (int j = 0; j < 4; j++) {
                float v  = acc[o][j];
                float sp = fmaxf(v, 0.f) + __logf(1.f + __expf(-fabsf(v)));
                yp[j] = sp;
#pragma unroll
                for (int rc = 0; rc < 4; rc++)
                    sacc[rc][j] = fmaf(swr[rc * 40 + oc], sp, sacc[rc][j]);
            }
            *(float4*)&g_y[(size_t)(b * 40 + oc) * L + l0 + tp] = yv;
        }
    }

#pragma unroll
    for (int rc = 0; rc < 4; rc++) {
        float4 sv = make_float4(sacc[rc][0], sacc[rc][1], sacc[rc][2], sacc[rc][3]);
        *(float4*)&g_s[(size_t)(b * 4 + rc) * L + l0 + tp] = sv;
    }
}

// ---------------------------------------------------------------------------
// Kernel 2: fftconv (4->4, K=401, pad 200) via tf32 mma  (R10 proven — frozen)
// ---------------------------------------------------------------------------
#define FT_POS   1024
#define FT_TH    128
#define FT_NT    8
#define FT_NJ    432
#define FT_WOFF  24
#define FT_WPAD  464
#define FT_XW    1472

__global__ __launch_bounds__(FT_TH)
void fftconv_kernel(const float* __restrict__ wf, const float* __restrict__ bf)
{
    __shared__ __align__(16) uint2 sx[FT_XW];
    __shared__ __align__(16) uint2 sw[4 * FT_WPAD];

    const int b    = blockIdx.y;
    const int TO0  = blockIdx.x * FT_POS;
    const int tid  = threadIdx.x;
    const int wid  = tid >> 5;
    const int lane = tid & 31;
    const int grp  = lane >> 2;
    const int tig  = lane & 3;
    const int wrel = wid * (FT_NT * 32);

    const int oc_lo = grp >> 2;
    const int oc_hi = oc_lo + 2;
    const int mp    = grp & 3;

    float acc[FT_NT][4];
    {
        float blo = bf[oc_lo], bhi = bf[oc_hi];
#pragma unroll
        for (int t = 0; t < FT_NT; t++) {
            acc[t][0] = blo; acc[t][1] = blo;
            acc[t][2] = bhi; acc[t][3] = bhi;
        }
    }

#pragma unroll 1
    for (int c = 0; c < 4; c++) {
        __syncthreads();
        for (int i = tid; i < 4 * FT_WPAD; i += FT_TH) {
            int oc = i / FT_WPAD;
            int r  = i - oc * FT_WPAD;
            int k0 = r - FT_WOFF;
            int k1 = k0 + 4;
            float v0 = (k0 >= 0 && k0 < 401) ? wf[(oc * 4 + c) * 401 + k0] : 0.f;
            float v1 = (k1 >= 0 && k1 < 401) ? wf[(oc * 4 + c) * 401 + k1] : 0.f;
            sw[i] = make_uint2(f2tf(v0), f2tf(v1));
        }
        {
            const float* sp = &g_s[(size_t)(b * 4 + c) * L];
            for (int i = tid; i < FT_XW; i += FT_TH) {
                int g  = TO0 - 200 + i;
                int g4 = g + 4;
                float v0 = (g  >= 0 && g  < L) ? sp[g]  : 0.f;
                float v1 = (g4 >= 0 && g4 < L) ? sp[g4] : 0.f;
                sx[i] = make_uint2(f2tf(v0), f2tf(v1));
            }
        }
        __syncthreads();

        const uint2* xw  = &sx[wrel];
        const uint2* wlo = &sw[oc_lo * FT_WPAD];
        const uint2* whi = &sw[oc_hi * FT_WPAD];
        int ai = FT_WOFF + tig - 8 * mp;
        int bi = grp + tig;
#pragma unroll 1
        for (int J0 = 0; J0 < FT_NJ; J0 += 8) {
            uint2 aLo = wlo[ai];
            uint2 aHi = whi[ai];
#pragma unroll
            for (int t = 0; t < FT_NT; t++) {
                uint2 bb = xw[bi + t * 32];
                mma_tf32(acc[t][0], acc[t][1], acc[t][2], acc[t][3],
                         aLo.x, aHi.x, aLo.y, aHi.y, bb.x, bb.y);
            }
            ai += 8; bi += 8;
        }
    }

    float* tlo = &g_t[(size_t)(b * 4 + oc_lo) * L];
    float* thi = &g_t[(size_t)(b * 4 + oc_hi) * L];
#pragma unroll
    for (int t = 0; t < FT_NT; t++) {
        int pos = TO0 + wrel + t * 32 + 8 * mp + 2 * tig;
        *(float2*)&tlo[pos] = make_float2(acc[t][0], acc[t][1]);
        *(float2*)&thi[pos] = make_float2(acc[t][2], acc[t][3]);
    }
}

// ---------------------------------------------------------------------------
// Kernel 3: expand (4->40, 1x1) + sigmoid gate * y  -> motifact  (frozen)
// ---------------------------------------------------------------------------
__global__ __launch_bounds__(256)
void gate_kernel(const float* __restrict__ we, const float* __restrict__ be)
{
    __shared__ float sw[160];
    __shared__ float sb[40];
    const int tid = threadIdx.x;
    if (tid < 160) sw[tid] = we[tid];
    if (tid < 40)  sb[tid] = be[tid];
    __syncthreads();

    const int b = blockIdx.y;
    const int l = (blockIdx.x * 256 + tid) * 4;

    float4 tv[4];
#pragma unroll
    for (int rc = 0; rc < 4; rc++)
        tv[rc] = *(const float4*)&g_t[(size_t)(b * 4 + rc) * L + l];

    for (int oc = 0; oc < 40; oc++) {
        float w0 = sw[oc * 4 + 0], w1 = sw[oc * 4 + 1];
        float w2 = sw[oc * 4 + 2], w3 = sw[oc * 4 + 3];
        float bb = sb[oc];
        float4 g;
        g.x = bb + w0 * tv[0].x + w1 * tv[1].x + w2 * tv[2].x + w3 * tv[3].x;
        g.y = bb + w0 * tv[0].y + w1 * tv[1].y + w2 * tv[2].y + w3 * tv[3].y;
        g.z = bb + w0 * tv[0].z + w1 * tv[1].z + w2 * tv[2].z + w3 * tv[3].z;
        g.w = bb + w0 * tv[0].w + w1 * tv[1].w + w2 * tv[2].w + w3 * tv[3].w;
        g.x = 1.f / (1.f + __expf(-g.x));
        g.y = 1.f / (1.f + __expf(-g.y));
        g.z = 1.f / (1.f + __expf(-g.z));
        g.w = 1.f / (1.f + __expf(-g.w));
        size_t idx = (size_t)(b * 40 + oc) * L + l;
        float4 yv = *(const float4*)&g_y[idx];
        float4 mv = make_float4(g.x * yv.x, g.y * yv.y, g.z * yv.z, g.w * yv.w);
        *(float4*)&g_m[idx] = mv;
    }
}

// ---------------------------------------------------------------------------
// Kernel 4: effect conv (40->2, K=601) via tf32 mma — R8 shape; weights
//   oc-paired in uint2 (A frag = 4 x LDS.64 instead of 8 x LDS.32; the x
//   window and its fill are EXACTLY R8's proven uint32 form).
// ---------------------------------------------------------------------------
#define ET_POS   2048       // positions per CTA
#define ET_TH    128
#define ET_WLEN  2656       // uint32 x-window entries per channel
#define ET_WPAD  864        // uint2 weight entries per cc (band at offset 128)
#define ET_CH    2          // channels per chunk
#define ET_NJ    728        // extended j range (91 chunks of 8)

__global__ __launch_bounds__(ET_TH)
void effect_kernel(const float* __restrict__ w, const float* __restrict__ bias,
                   float* __restrict__ out)
{
    __shared__ uint32_t sm_x[ET_CH * ET_WLEN];          // tf32 bits (R8 form)
    __shared__ __align__(16) uint2 sm_w[ET_CH * ET_WPAD]; // {w_oc0[k], w_oc1[k]}

    const int b    = blockIdx.y;
    const int LOc  = blockIdx.x * ET_POS;
    const int tid  = threadIdx.x;
    const int wid  = tid >> 5;
    const int lane = tid & 31;
    const int grp  = lane >> 2;
    const int tig  = lane & 3;
    const int wrel = wid * 512;

    float acc[4][2][4];
    const float b0v = bias[0], b1v = bias[1];
#pragma unroll
    for (int t = 0; t < 4; t++)
#pragma unroll
        for (int r = 0; r < 4; r++) { acc[t][0][r] = b0v; acc[t][1][r] = b1v; }

    for (int ch0 = 0; ch0 < 40; ch0 += ET_CH) {
        __syncthreads();
        // weights: band at offset 128, oc-paired, guarded single pass
        for (int i = tid; i < ET_CH * ET_WPAD; i += ET_TH) {
            int cc = i / ET_WPAD;
            int k  = (i - cc * ET_WPAD) - 128;
            float v0 = 0.f, v1 = 0.f;
            if (k >= 0 && k < 601) {
                v0 = w[((size_t)(0 * 40 + ch0 + cc)) * 601 + k];
                v1 = w[((size_t)(1 * 40 + ch0 + cc)) * 601 + k];
            }
            sm_w[i] = make_uint2(f2tf(v0), f2tf(v1));
        }
        // x window (R8 form): input idx = LOc + 200 + off, tf32-converted
        for (int i = tid; i < ET_CH * ET_WLEN; i += ET_TH) {
            int cc  = i / ET_WLEN;
            int off = i - cc * ET_WLEN;
            int g   = LOc + 200 + off;
            float v = (g < L) ? g_m[(size_t)(b * 40 + ch0 + cc) * L + g] : 0.f;
            sm_x[i] = f2tf(v);
        }
        __syncthreads();

#pragma unroll 1
        for (int cc = 0; cc < ET_CH; cc++) {
            const uint32_t* xw = &sm_x[cc * ET_WLEN + wrel];
            const uint2*    wp = &sm_w[cc * ET_WPAD];
            int ai = 128 + tig - 8 * grp;
            int bi = grp + tig;
#pragma unroll 1
            for (int J0 = 0; J0 < ET_NJ; J0 += 8) {
                uint2 A   = wp[ai];        // (a00, a10)
                uint2 Am  = wp[ai - 64];   // (a01, a11)
                uint2 A4  = wp[ai + 4];    // (a02, a12)
                uint2 A4m = wp[ai - 60];   // (a03, a13)
#pragma unroll
                for (int t = 0; t < 4; t++) {
                    uint32_t bb0 = xw[bi + t * 128];
                    uint32_t bb1 = xw[bi + t * 128 + 4];
                    mma_tf32(acc[t][0][0], acc[t][0][1], acc[t][0][2], acc[t][0][3],
                             A.x, Am.x, A4.x, A4m.x, bb0, bb1);
                    mma_tf32(acc[t][1][0], acc[t][1][1], acc[t][1][2], acc[t][1][3],
                             A.y, Am.y, A4.y, A4m.y, bb0, bb1);
                }
                ai += 8; bi += 8;
            }
        }
    }

#pragma unroll
    for (int t = 0; t < 4; t++) {
        int base = LOc + wrel + t * 128;
        int p0   = base + 8 * grp + 2 * tig;
        int p2   = p0 + 64;
#pragma unroll
        for (int oc = 0; oc < 2; oc++) {
            float* op = out + (size_t)(b * 2 + oc) * LOUT;
            float s0 = 1.f / (1.f + __expf(-acc[t][oc][0]));
            float s1 = 1.f / (1.f + __expf(-acc[t][oc][1]));
            float s2 = 1.f / (1.f + __expf(-acc[t][oc][2]));
            float s3 = 1.f / (1.f + __expf(-acc[t][oc][3]));
            if (p0 < LOUT)     op[p0]     = s0;
            if (p0 + 1 < LOUT) op[p0 + 1] = s1;
            if (p2 < LOUT)     op[p2]     = s2;
            if (p2 + 1 < LOUT) op[p2 + 1] = s3;
        }
    }
}

// ---------------------------------------------------------------------------
// Launch
// ---------------------------------------------------------------------------
extern "C" void kernel_launch(void* const* d_in, const int* in_sizes, int n_in,
                              void* d_out, int out_size)
{
    const float* x   = (const float*)d_in[0];
    const float* wm  = (const float*)d_in[1];
    const float* bm  = (const float*)d_in[2];
    const float* wr  = (const float*)d_in[3];
    const float* br  = (const float*)d_in[4];
    const float* wf  = (const float*)d_in[5];
    const float* bf  = (const float*)d_in[6];
    const float* wex = (const float*)d_in[7];
    const float* bex = (const float*)d_in[8];
    const float* wef = (const float*)d_in[9];
    const float* bef = (const float*)d_in[10];
    float* out = (float*)d_out;

    motif_kernel  <<<dim3(L / T1, B), TH1>>>(x, wm, bm, wr, br);
    fftconv_kernel<<<dim3(L / FT_POS, B), FT_TH>>>(wf, bf);
    gate_kernel   <<<dim3(L / 1024, B), 256>>>(wex, bex);
    effect_kernel <<<dim3((LOUT + ET_POS - 1) / ET_POS, B), ET_TH>>>(wef, bef, out);
}

// round 13
// speedup vs baseline: 1.2483x; 1.1000x over previous
#include <cuda_runtime.h>
#include <math.h>
#include <stdint.h>

// ---------------------------------------------------------------------------
// Shapes (fixed by the problem)
// ---------------------------------------------------------------------------
#define B    32
#define L    65536
#define LOUT 64536          // L - 1000 (slice [500:-500])

// Scratch (device globals; allocation in kernel_launch is forbidden)
__device__ float g_y[(size_t)B * 40 * L];   // motif output (post-softplus)
__device__ float g_s[(size_t)B * 4 * L];    // reduce output
__device__ float g_t[(size_t)B * 4 * L];    // fftconv output
__device__ float g_m[(size_t)B * 40 * L];   // motifact (gated)

// ---------------------------------------------------------------------------
// tf32 MMA helpers (shared)
// ---------------------------------------------------------------------------
__device__ __forceinline__ uint32_t f2tf(float v) {
    uint32_t r;
    asm("cvt.rna.tf32.f32 %0, %1;" : "=r"(r) : "f"(v));
    return r;
}

__device__ __forceinline__ void mma_tf32(float& d0, float& d1, float& d2, float& d3,
                                         uint32_t a0, uint32_t a1, uint32_t a2, uint32_t a3,
                                         uint32_t b0, uint32_t b1) {
    asm volatile(
        "mma.sync.aligned.m16n8k8.row.col.f32.tf32.tf32.f32 "
        "{%0,%1,%2,%3}, {%4,%5,%6,%7}, {%8,%9}, {%0,%1,%2,%3};\n"
        : "+f"(d0), "+f"(d1), "+f"(d2), "+f"(d3)
        : "r"(a0), "r"(a1), "r"(a2), "r"(a3), "r"(b0), "r"(b1));
}

__device__ __forceinline__ float softplusf(float v) {
    return fmaxf(v, 0.f) + __logf(1.f + __expf(-fabsf(v)));
}

// ---------------------------------------------------------------------------
// Kernel 1: motif conv (4->40, K=51, pad 25) + softplus, via tf32 MMA.
//   Dense GEMM: M = 16 oc-rows x 3 tiles (oc 0..47, rows >= 40 discarded),
//   reduction j = (c, k) with per-channel k padded 51 -> 56 (7 k8-chunks/c),
//   B Toeplitz window per channel: B[j][n] = x_c[pos0 + n + k - 25].
//   Weights: uint2 row-pairs {w[m*16+g], w[m*16+g+8]} at row stride 60
//   (conflict-free A loads). x window: uint2 {x[i], x[i+4]}.
//   Warp: 8 tiles x 8 pos = 64 positions; CTA (4 warps) = 256 positions.
// ---------------------------------------------------------------------------
#define MT_POS 256
#define MT_TH  128
#define MT_NT  8
#define MT_KS  60           // storage stride per (m,grp) row, uint2 units
#define MT_WN  (24 * MT_KS) // 1440 uint2
#define MT_XW  320          // uint2 x-window entries

__global__ __launch_bounds__(MT_TH)
void motif_kernel(const float* __restrict__ x,
                  const float* __restrict__ wm, const float* __restrict__ bm)
{
    __shared__ __align__(16) uint2 swt[MT_WN];   // weights, one channel
    __shared__ __align__(16) uint2 sxw[MT_XW];   // x window, one channel

    const int b    = blockIdx.y;
    const int LOc  = blockIdx.x * MT_POS;
    const int tid  = threadIdx.x;
    const int wid  = tid >> 5;
    const int lane = tid & 31;
    const int grp  = lane >> 2;
    const int tig  = lane & 3;
    const int wrel = wid * (MT_NT * 8);

    // acc[t][m]: c0,c1 = oc (m*16+grp) @ pos (2tig, 2tig+1); c2,c3 = oc+8
    float acc[MT_NT][3][4];
#pragma unroll
    for (int m = 0; m < 3; m++) {
        int oca = m * 16 + grp;
        int ocb = oca + 8;
        float ba = bm[oca];                       // oca <= 39 always
        float bb = (ocb < 40) ? bm[ocb] : 0.f;
#pragma unroll
        for (int t = 0; t < MT_NT; t++) {
            acc[t][m][0] = ba; acc[t][m][1] = ba;
            acc[t][m][2] = bb; acc[t][m][3] = bb;
        }
    }

#pragma unroll 1
    for (int c = 0; c < 4; c++) {
        __syncthreads();
        // weights for channel c: row-pairs, k zero-padded past 50
        for (int i = tid; i < MT_WN; i += MT_TH) {
            int mg = i / MT_KS;                  // m*8 + g
            int j  = i - mg * MT_KS;
            int m  = mg >> 3, g = mg & 7;
            int oca = m * 16 + g, ocb = oca + 8;
            float va = 0.f, vb = 0.f;
            if (j < 51) {
                va = wm[(oca * 4 + c) * 51 + j];
                if (ocb < 40) vb = wm[(ocb * 4 + c) * 51 + j];
            }
            swt[i] = make_uint2(f2tf(va), f2tf(vb));
        }
        // x window: sxw[i] = {x_c[LOc-25+i], x_c[LOc-25+i+4]}
        {
            const float* xc = &x[(size_t)(b * 4 + c) * L];
            for (int i = tid; i < MT_XW; i += MT_TH) {
                int g0 = LOc - 25 + i;
                int g4 = g0 + 4;
                float v0 = (g0 >= 0 && g0 < L) ? xc[g0] : 0.f;
                float v1 = (g4 >= 0 && g4 < L) ? xc[g4] : 0.f;
                sxw[i] = make_uint2(f2tf(v0), f2tf(v1));
            }
        }
        __syncthreads();

#pragma unroll 1
        for (int kc = 0; kc < 7; kc++) {
            uint2 aP[3], aQ[3];
#pragma unroll
            for (int m = 0; m < 3; m++) {
                int base = (m * 8 + grp) * MT_KS + kc * 8 + tig;
                aP[m] = swt[base];       // (a0, a1)
                aQ[m] = swt[base + 4];   // (a2, a3)
            }
            int bi = wrel + grp + tig + kc * 8;
#pragma unroll
            for (int t = 0; t < MT_NT; t++) {
                uint2 bb = sxw[bi + t * 8];
#pragma unroll
                for (int m = 0; m < 3; m++)
                    mma_tf32(acc[t][m][0], acc[t][m][1], acc[t][m][2], acc[t][m][3],
                             aP[m].x, aP[m].y, aQ[m].x, aQ[m].y, bb.x, bb.y);
            }
        }
    }

    // epilogue: softplus + write y (positions exactly tile the row; no guard)
#pragma unroll
    for (int t = 0; t < MT_NT; t++) {
        int p0 = LOc + wrel + t * 8 + 2 * tig;
#pragma unroll
        for (int m = 0; m < 3; m++) {
            int oca = m * 16 + grp;
            float2 ya = make_float2(softplusf(acc[t][m][0]), softplusf(acc[t][m][1]));
            *(float2*)&g_y[(size_t)(b * 40 + oca) * L + p0] = ya;
            if (m < 2) {
                int ocb = oca + 8;
                float2 yb = make_float2(softplusf(acc[t][m][2]), softplusf(acc[t][m][3]));
                *(float2*)&g_y[(size_t)(b * 40 + ocb) * L + p0] = yb;
            }
        }
    }
}

// ---------------------------------------------------------------------------
// Kernel 1b: reduce (40->4, 1x1) on y -> g_s   (memory-bound, ~60us)
// ---------------------------------------------------------------------------
__global__ __launch_bounds__(256)
void reduce_kernel(const float* __restrict__ wr, const float* __restrict__ br)
{
    __shared__ float sw[160];
    __shared__ float sb[4];
    const int tid = threadIdx.x;
    if (tid < 160) sw[tid] = wr[tid];
    if (tid < 4)   sb[tid] = br[tid];
    __syncthreads();

    const int b = blockIdx.y;
    const int l = (blockIdx.x * 256 + tid) * 4;

    float4 s[4];
#pragma unroll
    for (int rc = 0; rc < 4; rc++)
        s[rc] = make_float4(sb[rc], sb[rc], sb[rc], sb[rc]);

    for (int oc = 0; oc < 40; oc++) {
        float4 yv = *(const float4*)&g_y[(size_t)(b * 40 + oc) * L + l];
#pragma unroll
        for (int rc = 0; rc < 4; rc++) {
            float wv = sw[rc * 40 + oc];
            s[rc].x = fmaf(wv, yv.x, s[rc].x);
            s[rc].y = fmaf(wv, yv.y, s[rc].y);
            s[rc].z = fmaf(wv, yv.z, s[rc].z);
            s[rc].w = fmaf(wv, yv.w, s[rc].w);
        }
    }
#pragma unroll
    for (int rc = 0; rc < 4; rc++)
        *(float4*)&g_s[(size_t)(b * 4 + rc) * L + l] = s[rc];
}

// ---------------------------------------------------------------------------
// Kernel 2: fftconv (4->4, K=401, pad 200) via tf32 mma  (R10 proven — frozen)
// ---------------------------------------------------------------------------
#define FT_POS   1024
#define FT_TH    128
#define FT_NT    8
#define FT_NJ    432
#define FT_WOFF  24
#define FT_WPAD  464
#define FT_XW    1472

__global__ __launch_bounds__(FT_TH)
void fftconv_kernel(const float* __restrict__ wf, const float* __restrict__ bf)
{
    __shared__ __align__(16) uint2 sx[FT_XW];
    __shared__ __align__(16) uint2 sw[4 * FT_WPAD];

    const int b    = blockIdx.y;
    const int TO0  = blockIdx.x * FT_POS;
    const int tid  = threadIdx.x;
    const int wid  = tid >> 5;
    const int lane = tid & 31;
    const int grp  = lane >> 2;
    const int tig  = lane & 3;
    const int wrel = wid * (FT_NT * 32);

    const int oc_lo = grp >> 2;
    const int oc_hi = oc_lo + 2;
    const int mp    = grp & 3;

    float acc[FT_NT][4];
    {
        float blo = bf[oc_lo], bhi = bf[oc_hi];
#pragma unroll
        for (int t = 0; t < FT_NT; t++) {
            acc[t][0] = blo; acc[t][1] = blo;
            acc[t][2] = bhi; acc[t][3] = bhi;
        }
    }

#pragma unroll 1
    for (int c = 0; c < 4; c++) {
        __syncthreads();
        for (int i = tid; i < 4 * FT_WPAD; i += FT_TH) {
            int oc = i / FT_WPAD;
            int r  = i - oc * FT_WPAD;
            int k0 = r - FT_WOFF;
            int k1 = k0 + 4;
            float v0 = (k0 >= 0 && k0 < 401) ? wf[(oc * 4 + c) * 401 + k0] : 0.f;
            float v1 = (k1 >= 0 && k1 < 401) ? wf[(oc * 4 + c) * 401 + k1] : 0.f;
            sw[i] = make_uint2(f2tf(v0), f2tf(v1));
        }
        {
            const float* sp = &g_s[(size_t)(b * 4 + c) * L];
            for (int i = tid; i < FT_XW; i += FT_TH) {
                int g  = TO0 - 200 + i;
                int g4 = g + 4;
                float v0 = (g  >= 0 && g  < L) ? sp[g]  : 0.f;
                float v1 = (g4 >= 0 && g4 < L) ? sp[g4] : 0.f;
                sx[i] = make_uint2(f2tf(v0), f2tf(v1));
            }
        }
        __syncthreads();

        const uint2* xw  = &sx[wrel];
        const uint2* wlo = &sw[oc_lo * FT_WPAD];
        const uint2* whi = &sw[oc_hi * FT_WPAD];
        int ai = FT_WOFF + tig - 8 * mp;
        int bi = grp + tig;
#pragma unroll 1
        for (int J0 = 0; J0 < FT_NJ; J0 += 8) {
            uint2 aLo = wlo[ai];
            uint2 aHi = whi[ai];
#pragma unroll
            for (int t = 0; t < FT_NT; t++) {
                uint2 bb = xw[bi + t * 32];
                mma_tf32(acc[t][0], acc[t][1], acc[t][2], acc[t][3],
                         aLo.x, aHi.x, aLo.y, aHi.y, bb.x, bb.y);
            }
            ai += 8; bi += 8;
        }
    }

    float* tlo = &g_t[(size_t)(b * 4 + oc_lo) * L];
    float* thi = &g_t[(size_t)(b * 4 + oc_hi) * L];
#pragma unroll
    for (int t = 0; t < FT_NT; t++) {
        int pos = TO0 + wrel + t * 32 + 8 * mp + 2 * tig;
        *(float2*)&tlo[pos] = make_float2(acc[t][0], acc[t][1]);
        *(float2*)&thi[pos] = make_float2(acc[t][2], acc[t][3]);
    }
}

// ---------------------------------------------------------------------------
// Kernel 3: expand (4->40, 1x1) + sigmoid gate * y  -> motifact  (frozen)
// ---------------------------------------------------------------------------
__global__ __launch_bounds__(256)
void gate_kernel(const float* __restrict__ we, const float* __restrict__ be)
{
    __shared__ float sw[160];
    __shared__ float sb[40];
    const int tid = threadIdx.x;
    if (tid < 160) sw[tid] = we[tid];
    if (tid < 40)  sb[tid] = be[tid];
    __syncthreads();

    const int b = blockIdx.y;
    const int l = (blockIdx.x * 256 + tid) * 4;

    float4 tv[4];
#pragma unroll
    for (int rc = 0; rc < 4; rc++)
        tv[rc] = *(const float4*)&g_t[(size_t)(b * 4 + rc) * L + l];

    for (int oc = 0; oc < 40; oc++) {
        float w0 = sw[oc * 4 + 0], w1 = sw[oc * 4 + 1];
        float w2 = sw[oc * 4 + 2], w3 = sw[oc * 4 + 3];
        float bb = sb[oc];
        float4 g;
        g.x = bb + w0 * tv[0].x + w1 * tv[1].x + w2 * tv[2].x + w3 * tv[3].x;
        g.y = bb + w0 * tv[0].y + w1 * tv[1].y + w2 * tv[2].y + w3 * tv[3].y;
        g.z = bb + w0 * tv[0].z + w1 * tv[1].z + w2 * tv[2].z + w3 * tv[3].z;
        g.w = bb + w0 * tv[0].w + w1 * tv[1].w + w2 * tv[2].w + w3 * tv[3].w;
        g.x = 1.f / (1.f + __expf(-g.x));
        g.y = 1.f / (1.f + __expf(-g.y));
        g.z = 1.f / (1.f + __expf(-g.z));
        g.w = 1.f / (1.f + __expf(-g.w));
        size_t idx = (size_t)(b * 40 + oc) * L + l;
        float4 yv = *(const float4*)&g_y[idx];
        float4 mv = make_float4(g.x * yv.x, g.y * yv.y, g.z * yv.z, g.w * yv.w);
        *(float4*)&g_m[idx] = mv;
    }
}

// ---------------------------------------------------------------------------
// Kernel 4: effect conv (40->2, K=601) via tf32 mma  (R12 measured — frozen)
// ---------------------------------------------------------------------------
#define ET_POS   2048
#define ET_TH    128
#define ET_WLEN  2656
#define ET_WPAD  864
#define ET_CH    2
#define ET_NJ    728

__global__ __launch_bounds__(ET_TH)
void effect_kernel(const float* __restrict__ w, const float* __restrict__ bias,
                   float* __restrict__ out)
{
    __shared__ uint32_t sm_x[ET_CH * ET_WLEN];
    __shared__ __align__(16) uint2 sm_w[ET_CH * ET_WPAD];

    const int b    = blockIdx.y;
    const int LOc  = blockIdx.x * ET_POS;
    const int tid  = threadIdx.x;
    const int wid  = tid >> 5;
    const int lane = tid & 31;
    const int grp  = lane >> 2;
    const int tig  = lane & 3;
    const int wrel = wid * 512;

    float acc[4][2][4];
    const float b0v = bias[0], b1v = bias[1];
#pragma unroll
    for (int t = 0; t < 4; t++)
#pragma unroll
        for (int r = 0; r < 4; r++) { acc[t][0][r] = b0v; acc[t][1][r] = b1v; }

    for (int ch0 = 0; ch0 < 40; ch0 += ET_CH) {
        __syncthreads();
        for (int i = tid; i < ET_CH * ET_WPAD; i += ET_TH) {
            int cc = i / ET_WPAD;
            int k  = (i - cc * ET_WPAD) - 128;
            float v0 = 0.f, v1 = 0.f;
            if (k >= 0 && k < 601) {
                v0 = w[((size_t)(0 * 40 + ch0 + cc)) * 601 + k];
                v1 = w[((size_t)(1 * 40 + ch0 + cc)) * 601 + k];
            }
            sm_w[i] = make_uint2(f2tf(v0), f2tf(v1));
        }
        for (int i = tid; i < ET_CH * ET_WLEN; i += ET_TH) {
            int cc  = i / ET_WLEN;
            int off = i - cc * ET_WLEN;
            int g   = LOc + 200 + off;
            float v = (g < L) ? g_m[(size_t)(b * 40 + ch0 + cc) * L + g] : 0.f;
            sm_x[i] = f2tf(v);
        }
        __syncthreads();

#pragma unroll 1
        for (int cc = 0; cc < ET_CH; cc++) {
            const uint32_t* xw = &sm_x[cc * ET_WLEN + wrel];
            const uint2*    wp = &sm_w[cc * ET_WPAD];
            int ai = 128 + tig - 8 * grp;
            int bi = grp + tig;
#pragma unroll 1
            for (int J0 = 0; J0 < ET_NJ; J0 += 8) {
                uint2 A   = wp[ai];
                uint2 Am  = wp[ai - 64];
                uint2 A4  = wp[ai + 4];
                uint2 A4m = wp[ai - 60];
#pragma unroll
                for (int t = 0; t < 4; t++) {
                    uint32_t bb0 = xw[bi + t * 128];
                    uint32_t bb1 = xw[bi + t * 128 + 4];
                    mma_tf32(acc[t][0][0], acc[t][0][1], acc[t][0][2], acc[t][0][3],
                             A.x, Am.x, A4.x, A4m.x, bb0, bb1);
                    mma_tf32(acc[t][1][0], acc[t][1][1], acc[t][1][2], acc[t][1][3],
                             A.y, Am.y, A4.y, A4m.y, bb0, bb1);
                }
                ai += 8; bi += 8;
            }
        }
    }

#pragma unroll
    for (int t = 0; t < 4; t++) {
        int base = LOc + wrel + t * 128;
        int p0   = base + 8 * grp + 2 * tig;
        int p2   = p0 + 64;
#pragma unroll
        for (int oc = 0; oc < 2; oc++) {
            float* op = out + (size_t)(b * 2 + oc) * LOUT;
            float s0 = 1.f / (1.f + __expf(-acc[t][oc][0]));
            float s1 = 1.f / (1.f + __expf(-acc[t][oc][1]));
            float s2 = 1.f / (1.f + __expf(-acc[t][oc][2]));
            float s3 = 1.f / (1.f + __expf(-acc[t][oc][3]));
            if (p0 < LOUT)     op[p0]     = s0;
            if (p0 + 1 < LOUT) op[p0 + 1] = s1;
            if (p2 < LOUT)     op[p2]     = s2;
            if (p2 + 1 < LOUT) op[p2 + 1] = s3;
        }
    }
}

// ---------------------------------------------------------------------------
// Launch
// ---------------------------------------------------------------------------
extern "C" void kernel_launch(void* const* d_in, const int* in_sizes, int n_in,
                              void* d_out, int out_size)
{
    const float* x   = (const float*)d_in[0];
    const float* wm  = (const float*)d_in[1];
    const float* bm  = (const float*)d_in[2];
    const float* wr  = (const float*)d_in[3];
    const float* br  = (const float*)d_in[4];
    const float* wf  = (const float*)d_in[5];
    const float* bf  = (const float*)d_in[6];
    const float* wex = (const float*)d_in[7];
    const float* bex = (const float*)d_in[8];
    const float* wef = (const float*)d_in[9];
    const float* bef = (const float*)d_in[10];
    float* out = (float*)d_out;

    motif_kernel  <<<dim3(L / MT_POS, B), MT_TH>>>(x, wm, bm);
    reduce_kernel <<<dim3(L / 1024, B), 256>>>(wr, br);
    fftconv_kernel<<<dim3(L / FT_POS, B), FT_TH>>>(wf, bf);
    gate_kernel   <<<dim3(L / 1024, B), 256>>>(wex, bex);
    effect_kernel <<<dim3((LOUT + ET_POS - 1) / ET_POS, B), ET_TH>>>(wef, bef, out);
}

// round 14
// speedup vs baseline: 1.2694x; 1.0169x over previous
#include <cuda_runtime.h>
#include <math.h>
#include <stdint.h>

// ---------------------------------------------------------------------------
// Shapes (fixed by the problem)
// ---------------------------------------------------------------------------
#define B    32
#define L    65536
#define LOUT 64536          // L - 1000 (slice [500:-500])

// Scratch (device globals; allocation in kernel_launch is forbidden)
__device__ float g_y[(size_t)B * 40 * L];   // motif output (post-softplus)
__device__ float g_s[(size_t)B * 4 * L];    // reduce output
__device__ float g_t[(size_t)B * 4 * L];    // fftconv output
__device__ float g_m[(size_t)B * 40 * L];   // motifact (gated)

// ---------------------------------------------------------------------------
// tf32 MMA helpers (shared)
// ---------------------------------------------------------------------------
__device__ __forceinline__ uint32_t f2tf(float v) {
    uint32_t r;
    asm("cvt.rna.tf32.f32 %0, %1;" : "=r"(r) : "f"(v));
    return r;
}

__device__ __forceinline__ void mma_tf32(float& d0, float& d1, float& d2, float& d3,
                                         uint32_t a0, uint32_t a1, uint32_t a2, uint32_t a3,
                                         uint32_t b0, uint32_t b1) {
    asm volatile(
        "mma.sync.aligned.m16n8k8.row.col.f32.tf32.tf32.f32 "
        "{%0,%1,%2,%3}, {%4,%5,%6,%7}, {%8,%9}, {%0,%1,%2,%3};\n"
        : "+f"(d0), "+f"(d1), "+f"(d2), "+f"(d3)
        : "r"(a0), "r"(a1), "r"(a2), "r"(a3), "r"(b0), "r"(b1));
}

__device__ __forceinline__ float softplusf(float v) {
    return fmaxf(v, 0.f) + __logf(1.f + __expf(-fabsf(v)));
}

// ---------------------------------------------------------------------------
// Kernel 1: motif conv (4->40, K=51, pad 25) + softplus + FUSED reduce (40->4)
//   tf32 MMA, 256 threads (8 warps) x 512 positions per CTA.
//   Reduce: each lane owns the 5 channels == grp (mod 8); partials summed,
//   butterfly-shfl over grp lanes (masks 4/8/16), grp==0 stores g_s.
// ---------------------------------------------------------------------------
#define MT_POS 512
#define MT_TH  256
#define MT_NT  8
#define MT_KS  60           // storage stride per (m,grp) row, uint2 units
#define MT_WN  (24 * MT_KS) // 1440 uint2
#define MT_XW  576          // uint2 x-window entries

__global__ __launch_bounds__(MT_TH)
void motif_kernel(const float* __restrict__ x,
                  const float* __restrict__ wm, const float* __restrict__ bm,
                  const float* __restrict__ wr, const float* __restrict__ br)
{
    __shared__ __align__(16) uint2 swt[MT_WN];   // weights, one channel
    __shared__ __align__(16) uint2 sxw[MT_XW];   // x window, one channel
    __shared__ float srw[160];
    __shared__ float srb[4];

    const int b    = blockIdx.y;
    const int LOc  = blockIdx.x * MT_POS;
    const int tid  = threadIdx.x;
    const int wid  = tid >> 5;
    const int lane = tid & 31;
    const int grp  = lane >> 2;
    const int tig  = lane & 3;
    const int wrel = wid * (MT_NT * 8);

    if (tid < 160) srw[tid] = wr[tid];
    if (tid < 4)   srb[tid] = br[tid];

    // acc[t][m]: c0,c1 = oc (m*16+grp) @ pos (2tig, 2tig+1); c2,c3 = oc+8
    float acc[MT_NT][3][4];
#pragma unroll
    for (int m = 0; m < 3; m++) {
        int oca = m * 16 + grp;
        int ocb = oca + 8;
        float ba = bm[oca];
        float bb = (ocb < 40) ? bm[ocb] : 0.f;
#pragma unroll
        for (int t = 0; t < MT_NT; t++) {
            acc[t][m][0] = ba; acc[t][m][1] = ba;
            acc[t][m][2] = bb; acc[t][m][3] = bb;
        }
    }

#pragma unroll 1
    for (int c = 0; c < 4; c++) {
        __syncthreads();
        // weights for channel c: row-pairs {w[oc], w[oc+8]}, k padded past 50
        for (int i = tid; i < MT_WN; i += MT_TH) {
            int mg = i / MT_KS;                  // m*8 + g
            int j  = i - mg * MT_KS;
            int m  = mg >> 3, g = mg & 7;
            int oca = m * 16 + g, ocb = oca + 8;
            float va = 0.f, vb = 0.f;
            if (j < 51) {
                va = wm[(oca * 4 + c) * 51 + j];
                if (ocb < 40) vb = wm[(ocb * 4 + c) * 51 + j];
            }
            swt[i] = make_uint2(f2tf(va), f2tf(vb));
        }
        // x window: sxw[i] = {x_c[LOc-25+i], x_c[LOc-25+i+4]}
        {
            const float* xc = &x[(size_t)(b * 4 + c) * L];
            for (int i = tid; i < MT_XW; i += MT_TH) {
                int g0 = LOc - 25 + i;
                int g4 = g0 + 4;
                float v0 = (g0 >= 0 && g0 < L) ? xc[g0] : 0.f;
                float v1 = (g4 >= 0 && g4 < L) ? xc[g4] : 0.f;
                sxw[i] = make_uint2(f2tf(v0), f2tf(v1));
            }
        }
        __syncthreads();

#pragma unroll 1
        for (int kc = 0; kc < 7; kc++) {
            uint2 aP[3], aQ[3];
#pragma unroll
            for (int m = 0; m < 3; m++) {
                int base = (m * 8 + grp) * MT_KS + kc * 8 + tig;
                aP[m] = swt[base];       // (a0, a1)
                aQ[m] = swt[base + 4];   // (a2, a3)
            }
            int bi = wrel + grp + tig + kc * 8;
#pragma unroll
            for (int t = 0; t < MT_NT; t++) {
                uint2 bb = sxw[bi + t * 8];
#pragma unroll
                for (int m = 0; m < 3; m++)
                    mma_tf32(acc[t][m][0], acc[t][m][1], acc[t][m][2], acc[t][m][3],
                             aP[m].x, aP[m].y, aQ[m].x, aQ[m].y, bb.x, bb.y);
            }
        }
    }

    // epilogue: softplus + write y + fused reduce -> g_s
#pragma unroll 1
    for (int t = 0; t < MT_NT; t++) {
        int p0 = LOc + wrel + t * 8 + 2 * tig;
        float part[4][2];
#pragma unroll
        for (int rc = 0; rc < 4; rc++) { part[rc][0] = 0.f; part[rc][1] = 0.f; }

#pragma unroll
        for (int m = 0; m < 3; m++) {
            int oca = m * 16 + grp;
            float ya0 = softplusf(acc[t][m][0]);
            float ya1 = softplusf(acc[t][m][1]);
            *(float2*)&g_y[(size_t)(b * 40 + oca) * L + p0] = make_float2(ya0, ya1);
#pragma unroll
            for (int rc = 0; rc < 4; rc++) {
                float wv = srw[rc * 40 + oca];
                part[rc][0] = fmaf(wv, ya0, part[rc][0]);
                part[rc][1] = fmaf(wv, ya1, part[rc][1]);
            }
            if (m < 2) {
                int ocb = oca + 8;
                float yb0 = softplusf(acc[t][m][2]);
                float yb1 = softplusf(acc[t][m][3]);
                *(float2*)&g_y[(size_t)(b * 40 + ocb) * L + p0] = make_float2(yb0, yb1);
#pragma unroll
                for (int rc = 0; rc < 4; rc++) {
                    float wv = srw[rc * 40 + ocb];
                    part[rc][0] = fmaf(wv, yb0, part[rc][0]);
                    part[rc][1] = fmaf(wv, yb1, part[rc][1]);
                }
            }
        }
        // butterfly over grp lanes (lane-xor 4, 8, 16)
#pragma unroll
        for (int mask = 4; mask <= 16; mask <<= 1) {
#pragma unroll
            for (int rc = 0; rc < 4; rc++) {
                part[rc][0] += __shfl_xor_sync(0xffffffffu, part[rc][0], mask);
                part[rc][1] += __shfl_xor_sync(0xffffffffu, part[rc][1], mask);
            }
        }
        if (grp == 0) {
#pragma unroll
            for (int rc = 0; rc < 4; rc++) {
                float2 sv = make_float2(part[rc][0] + srb[rc], part[rc][1] + srb[rc]);
                *(float2*)&g_s[(size_t)(b * 4 + rc) * L + p0] = sv;
            }
        }
    }
}

// ---------------------------------------------------------------------------
// Kernel 2: fftconv (4->4, K=401, pad 200) via tf32 mma  (R10 proven — frozen)
// ---------------------------------------------------------------------------
#define FT_POS   1024
#define FT_TH    128
#define FT_NT    8
#define FT_NJ    432
#define FT_WOFF  24
#define FT_WPAD  464
#define FT_XW    1472

__global__ __launch_bounds__(FT_TH)
void fftconv_kernel(const float* __restrict__ wf, const float* __restrict__ bf)
{
    __shared__ __align__(16) uint2 sx[FT_XW];
    __shared__ __align__(16) uint2 sw[4 * FT_WPAD];

    const int b    = blockIdx.y;
    const int TO0  = blockIdx.x * FT_POS;
    const int tid  = threadIdx.x;
    const int wid  = tid >> 5;
    const int lane = tid & 31;
    const int grp  = lane >> 2;
    const int tig  = lane & 3;
    const int wrel = wid * (FT_NT * 32);

    const int oc_lo = grp >> 2;
    const int oc_hi = oc_lo + 2;
    const int mp    = grp & 3;

    float acc[FT_NT][4];
    {
        float blo = bf[oc_lo], bhi = bf[oc_hi];
#pragma unroll
        for (int t = 0; t < FT_NT; t++) {
            acc[t][0] = blo; acc[t][1] = blo;
            acc[t][2] = bhi; acc[t][3] = bhi;
        }
    }

#pragma unroll 1
    for (int c = 0; c < 4; c++) {
        __syncthreads();
        for (int i = tid; i < 4 * FT_WPAD; i += FT_TH) {
            int oc = i / FT_WPAD;
            int r  = i - oc * FT_WPAD;
            int k0 = r - FT_WOFF;
            int k1 = k0 + 4;
            float v0 = (k0 >= 0 && k0 < 401) ? wf[(oc * 4 + c) * 401 + k0] : 0.f;
            float v1 = (k1 >= 0 && k1 < 401) ? wf[(oc * 4 + c) * 401 + k1] : 0.f;
            sw[i] = make_uint2(f2tf(v0), f2tf(v1));
        }
        {
            const float* sp = &g_s[(size_t)(b * 4 + c) * L];
            for (int i = tid; i < FT_XW; i += FT_TH) {
                int g  = TO0 - 200 + i;
                int g4 = g + 4;
                float v0 = (g  >= 0 && g  < L) ? sp[g]  : 0.f;
                float v1 = (g4 >= 0 && g4 < L) ? sp[g4] : 0.f;
                sx[i] = make_uint2(f2tf(v0), f2tf(v1));
            }
        }
        __syncthreads();

        const uint2* xw  = &sx[wrel];
        const uint2* wlo = &sw[oc_lo * FT_WPAD];
        const uint2* whi = &sw[oc_hi * FT_WPAD];
        int ai = FT_WOFF + tig - 8 * mp;
        int bi = grp + tig;
#pragma unroll 1
        for (int J0 = 0; J0 < FT_NJ; J0 += 8) {
            uint2 aLo = wlo[ai];
            uint2 aHi = whi[ai];
#pragma unroll
            for (int t = 0; t < FT_NT; t++) {
                uint2 bb = xw[bi + t * 32];
                mma_tf32(acc[t][0], acc[t][1], acc[t][2], acc[t][3],
                         aLo.x, aHi.x, aLo.y, aHi.y, bb.x, bb.y);
            }
            ai += 8; bi += 8;
        }
    }

    float* tlo = &g_t[(size_t)(b * 4 + oc_lo) * L];
    float* thi = &g_t[(size_t)(b * 4 + oc_hi) * L];
#pragma unroll
    for (int t = 0; t < FT_NT; t++) {
        int pos = TO0 + wrel + t * 32 + 8 * mp + 2 * tig;
        *(float2*)&tlo[pos] = make_float2(acc[t][0], acc[t][1]);
        *(float2*)&thi[pos] = make_float2(acc[t][2], acc[t][3]);
    }
}

// ---------------------------------------------------------------------------
// Kernel 3: expand (4->40, 1x1) + sigmoid gate * y  -> motifact
//   8 positions per thread (2x float4) for more MLP toward HBM roofline.
// ---------------------------------------------------------------------------
__global__ __launch_bounds__(256)
void gate_kernel(const float* __restrict__ we, const float* __restrict__ be)
{
    __shared__ float sw[160];
    __shared__ float sb[40];
    const int tid = threadIdx.x;
    if (tid < 160) sw[tid] = we[tid];
    if (tid < 40)  sb[tid] = be[tid];
    __syncthreads();

    const int b = blockIdx.y;
    const int l = (blockIdx.x * 256 + tid) * 8;

    float4 tv[4][2];
#pragma unroll
    for (int rc = 0; rc < 4; rc++) {
        tv[rc][0] = *(const float4*)&g_t[(size_t)(b * 4 + rc) * L + l];
        tv[rc][1] = *(const float4*)&g_t[(size_t)(b * 4 + rc) * L + l + 4];
    }

    for (int oc = 0; oc < 40; oc++) {
        float w0 = sw[oc * 4 + 0], w1 = sw[oc * 4 + 1];
        float w2 = sw[oc * 4 + 2], w3 = sw[oc * 4 + 3];
        float bb = sb[oc];
        size_t idx = (size_t)(b * 40 + oc) * L + l;
#pragma unroll
        for (int h = 0; h < 2; h++) {
            float4 g;
            g.x = bb + w0 * tv[0][h].x + w1 * tv[1][h].x + w2 * tv[2][h].x + w3 * tv[3][h].x;
            g.y = bb + w0 * tv[0][h].y + w1 * tv[1][h].y + w2 * tv[2][h].y + w3 * tv[3][h].y;
            g.z = bb + w0 * tv[0][h].z + w1 * tv[1][h].z + w2 * tv[2][h].z + w3 * tv[3][h].z;
            g.w = bb + w0 * tv[0][h].w + w1 * tv[1][h].w + w2 * tv[2][h].w + w3 * tv[3][h].w;
            g.x = 1.f / (1.f + __expf(-g.x));
            g.y = 1.f / (1.f + __expf(-g.y));
            g.z = 1.f / (1.f + __expf(-g.z));
            g.w = 1.f / (1.f + __expf(-g.w));
            float4 yv = *(const float4*)&g_y[idx + h * 4];
            float4 mv = make_float4(g.x * yv.x, g.y * yv.y, g.z * yv.z, g.w * yv.w);
            *(float4*)&g_m[idx + h * 4] = mv;
        }
    }
}

// ---------------------------------------------------------------------------
// Kernel 4: effect conv (40->2, K=601) via tf32 mma  (R12 measured — frozen)
// ---------------------------------------------------------------------------
#define ET_POS   2048
#define ET_TH    128
#define ET_WLEN  2656
#define ET_WPAD  864
#define ET_CH    2
#define ET_NJ    728

__global__ __launch_bounds__(ET_TH)
void effect_kernel(const float* __restrict__ w, const float* __restrict__ bias,
                   float* __restrict__ out)
{
    __shared__ uint32_t sm_x[ET_CH * ET_WLEN];
    __shared__ __align__(16) uint2 sm_w[ET_CH * ET_WPAD];

    const int b    = blockIdx.y;
    const int LOc  = blockIdx.x * ET_POS;
    const int tid  = threadIdx.x;
    const int wid  = tid >> 5;
    const int lane = tid & 31;
    const int grp  = lane >> 2;
    const int tig  = lane & 3;
    const int wrel = wid * 512;

    float acc[4][2][4];
    const float b0v = bias[0], b1v = bias[1];
#pragma unroll
    for (int t = 0; t < 4; t++)
#pragma unroll
        for (int r = 0; r < 4; r++) { acc[t][0][r] = b0v; acc[t][1][r] = b1v; }

    for (int ch0 = 0; ch0 < 40; ch0 += ET_CH) {
        __syncthreads();
        for (int i = tid; i < ET_CH * ET_WPAD; i += ET_TH) {
            int cc = i / ET_WPAD;
            int k  = (i - cc * ET_WPAD) - 128;
            float v0 = 0.f, v1 = 0.f;
            if (k >= 0 && k < 601) {
                v0 = w[((size_t)(0 * 40 + ch0 + cc)) * 601 + k];
                v1 = w[((size_t)(1 * 40 + ch0 + cc)) * 601 + k];
            }
            sm_w[i] = make_uint2(f2tf(v0), f2tf(v1));
        }
        for (int i = tid; i < ET_CH * ET_WLEN; i += ET_TH) {
            int cc  = i / ET_WLEN;
            int off = i - cc * ET_WLEN;
            int g   = LOc + 200 + off;
            float v = (g < L) ? g_m[(size_t)(b * 40 + ch0 + cc) * L + g] : 0.f;
            sm_x[i] = f2tf(v);
        }
        __syncthreads();

#pragma unroll 1
        for (int cc = 0; cc < ET_CH; cc++) {
            const uint32_t* xw = &sm_x[cc * ET_WLEN + wrel];
            const uint2*    wp = &sm_w[cc * ET_WPAD];
            int ai = 128 + tig - 8 * grp;
            int bi = grp + tig;
#pragma unroll 1
            for (int J0 = 0; J0 < ET_NJ; J0 += 8) {
                uint2 A   = wp[ai];
                uint2 Am  = wp[ai - 64];
                uint2 A4  = wp[ai + 4];
                uint2 A4m = wp[ai - 60];
#pragma unroll
                for (int t = 0; t < 4; t++) {
                    uint32_t bb0 = xw[bi + t * 128];
                    uint32_t bb1 = xw[bi + t * 128 + 4];
                    mma_tf32(acc[t][0][0], acc[t][0][1], acc[t][0][2], acc[t][0][3],
                             A.x, Am.x, A4.x, A4m.x, bb0, bb1);
                    mma_tf32(acc[t][1][0], acc[t][1][1], acc[t][1][2], acc[t][1][3],
                             A.y, Am.y, A4.y, A4m.y, bb0, bb1);
                }
                ai += 8; bi += 8;
            }
        }
    }

#pragma unroll
    for (int t = 0; t < 4; t++) {
        int base = LOc + wrel + t * 128;
        int p0   = base + 8 * grp + 2 * tig;
        int p2   = p0 + 64;
#pragma unroll
        for (int oc = 0; oc < 2; oc++) {
            float* op = out + (size_t)(b * 2 + oc) * LOUT;
            float s0 = 1.f / (1.f + __expf(-acc[t][oc][0]));
            float s1 = 1.f / (1.f + __expf(-acc[t][oc][1]));
            float s2 = 1.f / (1.f + __expf(-acc[t][oc][2]));
            float s3 = 1.f / (1.f + __expf(-acc[t][oc][3]));
            if (p0 < LOUT)     op[p0]     = s0;
            if (p0 + 1 < LOUT) op[p0 + 1] = s1;
            if (p2 < LOUT)     op[p2]     = s2;
            if (p2 + 1 < LOUT) op[p2 + 1] = s3;
        }
    }
}

// ---------------------------------------------------------------------------
// Launch
// ---------------------------------------------------------------------------
extern "C" void kernel_launch(void* const* d_in, const int* in_sizes, int n_in,
                              void* d_out, int out_size)
{
    const float* x   = (const float*)d_in[0];
    const float* wm  = (const float*)d_in[1];
    const float* bm  = (const float*)d_in[2];
    const float* wr  = (const float*)d_in[3];
    const float* br  = (const float*)d_in[4];
    const float* wf  = (const float*)d_in[5];
    const float* bf  = (const float*)d_in[6];
    const float* wex = (const float*)d_in[7];
    const float* bex = (const float*)d_in[8];
    const float* wef = (const float*)d_in[9];
    const float* bef = (const float*)d_in[10];
    float* out = (float*)d_out;

    motif_kernel  <<<dim3(L / MT_POS, B), MT_TH>>>(x, wm, bm, wr, br);
    fftconv_kernel<<<dim3(L / FT_POS, B), FT_TH>>>(wf, bf);
    gate_kernel   <<<dim3(L / 2048, B), 256>>>(wex, bex);
    effect_kernel <<<dim3((LOUT + ET_POS - 1) / ET_POS, B), ET_TH>>>(wef, bef, out);
}

// round 16
// speedup vs baseline: 1.4449x; 1.1383x over previous
#include <cuda_runtime.h>
#include <math.h>
#include <stdint.h>

// ---------------------------------------------------------------------------
// Shapes (fixed by the problem)
// ---------------------------------------------------------------------------
#define B    32
#define L    65536
#define LOUT 64536          // L - 1000 (slice [500:-500])
#define PSTR 65536          // padded stride for effect partial buffers

// Scratch (device globals; allocation in kernel_launch is forbidden)
__device__ float g_y[(size_t)B * 40 * L];   // motif output (post-softplus)
__device__ float g_s[(size_t)B * 4 * L];    // reduce output
__device__ float g_t[(size_t)B * 4 * L];    // fftconv output
__device__ float g_m[(size_t)B * 40 * L];   // motifact (gated)
__device__ float g_p[2][(size_t)B * 2 * PSTR]; // effect partial sums (ch halves)

// ---------------------------------------------------------------------------
// tf32 MMA helpers (shared)
// ---------------------------------------------------------------------------
__device__ __forceinline__ uint32_t f2tf(float v) {
    uint32_t r;
    asm("cvt.rna.tf32.f32 %0, %1;" : "=r"(r) : "f"(v));
    return r;
}

__device__ __forceinline__ void mma_tf32(float& d0, float& d1, float& d2, float& d3,
                                         uint32_t a0, uint32_t a1, uint32_t a2, uint32_t a3,
                                         uint32_t b0, uint32_t b1) {
    asm volatile(
        "mma.sync.aligned.m16n8k8.row.col.f32.tf32.tf32.f32 "
        "{%0,%1,%2,%3}, {%4,%5,%6,%7}, {%8,%9}, {%0,%1,%2,%3};\n"
        : "+f"(d0), "+f"(d1), "+f"(d2), "+f"(d3)
        : "r"(a0), "r"(a1), "r"(a2), "r"(a3), "r"(b0), "r"(b1));
}

__device__ __forceinline__ float softplusf(float v) {
    return fmaxf(v, 0.f) + __logf(1.f + __expf(-fabsf(v)));
}

// ---------------------------------------------------------------------------
// Kernel 1: motif conv (4->40, K=51, pad 25) + softplus + FUSED reduce (40->4)
//   (R14 measured — frozen)
// ---------------------------------------------------------------------------
#define MT_POS 512
#define MT_TH  256
#define MT_NT  8
#define MT_KS  60
#define MT_WN  (24 * MT_KS)
#define MT_XW  576

__global__ __launch_bounds__(MT_TH)
void motif_kernel(const float* __restrict__ x,
                  const float* __restrict__ wm, const float* __restrict__ bm,
                  const float* __restrict__ wr, const float* __restrict__ br)
{
    __shared__ __align__(16) uint2 swt[MT_WN];
    __shared__ __align__(16) uint2 sxw[MT_XW];
    __shared__ float srw[160];
    __shared__ float srb[4];

    const int b    = blockIdx.y;
    const int LOc  = blockIdx.x * MT_POS;
    const int tid  = threadIdx.x;
    const int wid  = tid >> 5;
    const int lane = tid & 31;
    const int grp  = lane >> 2;
    const int tig  = lane & 3;
    const int wrel = wid * (MT_NT * 8);

    if (tid < 160) srw[tid] = wr[tid];
    if (tid < 4)   srb[tid] = br[tid];

    float acc[MT_NT][3][4];
#pragma unroll
    for (int m = 0; m < 3; m++) {
        int oca = m * 16 + grp;
        int ocb = oca + 8;
        float ba = bm[oca];
        float bb = (ocb < 40) ? bm[ocb] : 0.f;
#pragma unroll
        for (int t = 0; t < MT_NT; t++) {
            acc[t][m][0] = ba; acc[t][m][1] = ba;
            acc[t][m][2] = bb; acc[t][m][3] = bb;
        }
    }

#pragma unroll 1
    for (int c = 0; c < 4; c++) {
        __syncthreads();
        for (int i = tid; i < MT_WN; i += MT_TH) {
            int mg = i / MT_KS;
            int j  = i - mg * MT_KS;
            int m  = mg >> 3, g = mg & 7;
            int oca = m * 16 + g, ocb = oca + 8;
            float va = 0.f, vb = 0.f;
            if (j < 51) {
                va = wm[(oca * 4 + c) * 51 + j];
                if (ocb < 40) vb = wm[(ocb * 4 + c) * 51 + j];
            }
            swt[i] = make_uint2(f2tf(va), f2tf(vb));
        }
        {
            const float* xc = &x[(size_t)(b * 4 + c) * L];
            for (int i = tid; i < MT_XW; i += MT_TH) {
                int g0 = LOc - 25 + i;
                int g4 = g0 + 4;
                float v0 = (g0 >= 0 && g0 < L) ? xc[g0] : 0.f;
                float v1 = (g4 >= 0 && g4 < L) ? xc[g4] : 0.f;
                sxw[i] = make_uint2(f2tf(v0), f2tf(v1));
            }
        }
        __syncthreads();

#pragma unroll 1
        for (int kc = 0; kc < 7; kc++) {
            uint2 aP[3], aQ[3];
#pragma unroll
            for (int m = 0; m < 3; m++) {
                int base = (m * 8 + grp) * MT_KS + kc * 8 + tig;
                aP[m] = swt[base];
                aQ[m] = swt[base + 4];
            }
            int bi = wrel + grp + tig + kc * 8;
#pragma unroll
            for (int t = 0; t < MT_NT; t++) {
                uint2 bb = sxw[bi + t * 8];
#pragma unroll
                for (int m = 0; m < 3; m++)
                    mma_tf32(acc[t][m][0], acc[t][m][1], acc[t][m][2], acc[t][m][3],
                             aP[m].x, aP[m].y, aQ[m].x, aQ[m].y, bb.x, bb.y);
            }
        }
    }

#pragma unroll 1
    for (int t = 0; t < MT_NT; t++) {
        int p0 = LOc + wrel + t * 8 + 2 * tig;
        float part[4][2];
#pragma unroll
        for (int rc = 0; rc < 4; rc++) { part[rc][0] = 0.f; part[rc][1] = 0.f; }

#pragma unroll
        for (int m = 0; m < 3; m++) {
            int oca = m * 16 + grp;
            float ya0 = softplusf(acc[t][m][0]);
            float ya1 = softplusf(acc[t][m][1]);
            *(float2*)&g_y[(size_t)(b * 40 + oca) * L + p0] = make_float2(ya0, ya1);
#pragma unroll
            for (int rc = 0; rc < 4; rc++) {
                float wv = srw[rc * 40 + oca];
                part[rc][0] = fmaf(wv, ya0, part[rc][0]);
                part[rc][1] = fmaf(wv, ya1, part[rc][1]);
            }
            if (m < 2) {
                int ocb = oca + 8;
                float yb0 = softplusf(acc[t][m][2]);
                float yb1 = softplusf(acc[t][m][3]);
                *(float2*)&g_y[(size_t)(b * 40 + ocb) * L + p0] = make_float2(yb0, yb1);
#pragma unroll
                for (int rc = 0; rc < 4; rc++) {
                    float wv = srw[rc * 40 + ocb];
                    part[rc][0] = fmaf(wv, yb0, part[rc][0]);
                    part[rc][1] = fmaf(wv, yb1, part[rc][1]);
                }
            }
        }
#pragma unroll
        for (int mask = 4; mask <= 16; mask <<= 1) {
#pragma unroll
            for (int rc = 0; rc < 4; rc++) {
                part[rc][0] += __shfl_xor_sync(0xffffffffu, part[rc][0], mask);
                part[rc][1] += __shfl_xor_sync(0xffffffffu, part[rc][1], mask);
            }
        }
        if (grp == 0) {
#pragma unroll
            for (int rc = 0; rc < 4; rc++) {
                float2 sv = make_float2(part[rc][0] + srb[rc], part[rc][1] + srb[rc]);
                *(float2*)&g_s[(size_t)(b * 4 + rc) * L + p0] = sv;
            }
        }
    }
}

// ---------------------------------------------------------------------------
// Kernel 2: fftconv (4->4, K=401, pad 200) via tf32 mma  (R10 proven — frozen)
// ---------------------------------------------------------------------------
#define FT_POS   1024
#define FT_TH    128
#define FT_NT    8
#define FT_NJ    432
#define FT_WOFF  24
#define FT_WPAD  464
#define FT_XW    1472

__global__ __launch_bounds__(FT_TH)
void fftconv_kernel(const float* __restrict__ wf, const float* __restrict__ bf)
{
    __shared__ __align__(16) uint2 sx[FT_XW];
    __shared__ __align__(16) uint2 sw[4 * FT_WPAD];

    const int b    = blockIdx.y;
    const int TO0  = blockIdx.x * FT_POS;
    const int tid  = threadIdx.x;
    const int wid  = tid >> 5;
    const int lane = tid & 31;
    const int grp  = lane >> 2;
    const int tig  = lane & 3;
    const int wrel = wid * (FT_NT * 32);

    const int oc_lo = grp >> 2;
    const int oc_hi = oc_lo + 2;
    const int mp    = grp & 3;

    float acc[FT_NT][4];
    {
        float blo = bf[oc_lo], bhi = bf[oc_hi];
#pragma unroll
        for (int t = 0; t < FT_NT; t++) {
            acc[t][0] = blo; acc[t][1] = blo;
            acc[t][2] = bhi; acc[t][3] = bhi;
        }
    }

#pragma unroll 1
    for (int c = 0; c < 4; c++) {
        __syncthreads();
        for (int i = tid; i < 4 * FT_WPAD; i += FT_TH) {
            int oc = i / FT_WPAD;
            int r  = i - oc * FT_WPAD;
            int k0 = r - FT_WOFF;
            int k1 = k0 + 4;
            float v0 = (k0 >= 0 && k0 < 401) ? wf[(oc * 4 + c) * 401 + k0] : 0.f;
            float v1 = (k1 >= 0 && k1 < 401) ? wf[(oc * 4 + c) * 401 + k1] : 0.f;
            sw[i] = make_uint2(f2tf(v0), f2tf(v1));
        }
        {
            const float* sp = &g_s[(size_t)(b * 4 + c) * L];
            for (int i = tid; i < FT_XW; i += FT_TH) {
                int g  = TO0 - 200 + i;
                int g4 = g + 4;
                float v0 = (g  >= 0 && g  < L) ? sp[g]  : 0.f;
                float v1 = (g4 >= 0 && g4 < L) ? sp[g4] : 0.f;
                sx[i] = make_uint2(f2tf(v0), f2tf(v1));
            }
        }
        __syncthreads();

        const uint2* xw  = &sx[wrel];
        const uint2* wlo = &sw[oc_lo * FT_WPAD];
        const uint2* whi = &sw[oc_hi * FT_WPAD];
        int ai = FT_WOFF + tig - 8 * mp;
        int bi = grp + tig;
#pragma unroll 1
        for (int J0 = 0; J0 < FT_NJ; J0 += 8) {
            uint2 aLo = wlo[ai];
            uint2 aHi = whi[ai];
#pragma unroll
            for (int t = 0; t < FT_NT; t++) {
                uint2 bb = xw[bi + t * 32];
                mma_tf32(acc[t][0], acc[t][1], acc[t][2], acc[t][3],
                         aLo.x, aHi.x, aLo.y, aHi.y, bb.x, bb.y);
            }
            ai += 8; bi += 8;
        }
    }

    float* tlo = &g_t[(size_t)(b * 4 + oc_lo) * L];
    float* thi = &g_t[(size_t)(b * 4 + oc_hi) * L];
#pragma unroll
    for (int t = 0; t < FT_NT; t++) {
        int pos = TO0 + wrel + t * 32 + 8 * mp + 2 * tig;
        *(float2*)&tlo[pos] = make_float2(acc[t][0], acc[t][1]);
        *(float2*)&thi[pos] = make_float2(acc[t][2], acc[t][3]);
    }
}

// ---------------------------------------------------------------------------
// Kernel 3: expand (4->40, 1x1) + sigmoid gate * y -> motifact (R14 — frozen)
// ---------------------------------------------------------------------------
__global__ __launch_bounds__(256)
void gate_kernel(const float* __restrict__ we, const float* __restrict__ be)
{
    __shared__ float sw[160];
    __shared__ float sb[40];
    const int tid = threadIdx.x;
    if (tid < 160) sw[tid] = we[tid];
    if (tid < 40)  sb[tid] = be[tid];
    __syncthreads();

    const int b = blockIdx.y;
    const int l = (blockIdx.x * 256 + tid) * 8;

    float4 tv[4][2];
#pragma unroll
    for (int rc = 0; rc < 4; rc++) {
        tv[rc][0] = *(const float4*)&g_t[(size_t)(b * 4 + rc) * L + l];
        tv[rc][1] = *(const float4*)&g_t[(size_t)(b * 4 + rc) * L + l + 4];
    }

    for (int oc = 0; oc < 40; oc++) {
        float w0 = sw[oc * 4 + 0], w1 = sw[oc * 4 + 1];
        float w2 = sw[oc * 4 + 2], w3 = sw[oc * 4 + 3];
        float bb = sb[oc];
        size_t idx = (size_t)(b * 40 + oc) * L + l;
#pragma unroll
        for (int h = 0; h < 2; h++) {
            float4 g;
            g.x = bb + w0 * tv[0][h].x + w1 * tv[1][h].x + w2 * tv[2][h].x + w3 * tv[3][h].x;
            g.y = bb + w0 * tv[0][h].y + w1 * tv[1][h].y + w2 * tv[2][h].y + w3 * tv[3][h].y;
            g.z = bb + w0 * tv[0][h].z + w1 * tv[1][h].z + w2 * tv[2][h].z + w3 * tv[3][h].z;
            g.w = bb + w0 * tv[0][h].w + w1 * tv[1][h].w + w2 * tv[2][h].w + w3 * tv[3][h].w;
            g.x = 1.f / (1.f + __expf(-g.x));
            g.y = 1.f / (1.f + __expf(-g.y));
            g.z = 1.f / (1.f + __expf(-g.z));
            g.w = 1.f / (1.f + __expf(-g.w));
            float4 yv = *(const float4*)&g_y[idx + h * 4];
            float4 mv = make_float4(g.x * yv.x, g.y * yv.y, g.z * yv.z, g.w * yv.w);
            *(float4*)&g_m[idx + h * 4] = mv;
        }
    }
}

// ---------------------------------------------------------------------------
// Kernel 4: effect conv (40->2, K=601) via tf32 mma, NT=8 + channel-split.
//   gridDim.z = 2 channel halves (20 ch each); each CTA covers 4096 positions.
//   Raw partial sums to g_p[z] (padded stride, no guards). A-frag reuse over
//   8 tiles -> 1.5 smem wavefronts/MMA (vs 2.0 at NT=4).
// ---------------------------------------------------------------------------
#define EM_POS   4096       // positions per CTA
#define EM_TH    128
#define EM_NT    8          // 128-pos tiles per warp
#define EM_WLEN  4704       // uint32 x-window entries
#define EM_WPAD  864        // uint2 weight entries (band at offset 128)
#define EM_NJ    728        // extended j range (91 chunks of 8)

__global__ __launch_bounds__(EM_TH)
void effect_main(const float* __restrict__ w, const float* __restrict__ bias)
{
    __shared__ uint32_t sm_x[EM_WLEN];
    __shared__ __align__(16) uint2 sm_w[EM_WPAD];   // {w_oc0[k], w_oc1[k]}

    const int b    = blockIdx.y;
    const int z    = blockIdx.z;                    // channel half
    const int LOc  = blockIdx.x * EM_POS;
    const int tid  = threadIdx.x;
    const int wid  = tid >> 5;
    const int lane = tid & 31;
    const int grp  = lane >> 2;
    const int tig  = lane & 3;
    const int wrel = wid * (EM_NT * 128);           // 1024 positions per warp

    float acc[EM_NT][2][4];
    const float b0v = (z == 0) ? bias[0] : 0.f;
    const float b1v = (z == 0) ? bias[1] : 0.f;
#pragma unroll
    for (int t = 0; t < EM_NT; t++)
#pragma unroll
        for (int r = 0; r < 4; r++) { acc[t][0][r] = b0v; acc[t][1][r] = b1v; }

#pragma unroll 1
    for (int ch = 0; ch < 20; ch++) {
        const int chg = z * 20 + ch;
        __syncthreads();
        // weights: band at offset 128, oc-paired
        for (int i = tid; i < EM_WPAD; i += EM_TH) {
            int k = i - 128;
            float v0 = 0.f, v1 = 0.f;
            if (k >= 0 && k < 601) {
                v0 = w[((size_t)(0 * 40 + chg)) * 601 + k];
                v1 = w[((size_t)(1 * 40 + chg)) * 601 + k];
            }
            sm_w[i] = make_uint2(f2tf(v0), f2tf(v1));
        }
        // x window
        {
            const float* xm = &g_m[(size_t)(b * 40 + chg) * L];
            for (int i = tid; i < EM_WLEN; i += EM_TH) {
                int g   = LOc + 200 + i;
                float v = (g < L) ? xm[g] : 0.f;
                sm_x[i] = f2tf(v);
            }
        }
        __syncthreads();

        const uint32_t* xw = &sm_x[wrel];
        int ai = 128 + tig - 8 * grp;
        int bi = grp + tig;
#pragma unroll 1
        for (int J0 = 0; J0 < EM_NJ; J0 += 8) {
            uint2 A   = sm_w[ai];        // (a00, a10)
            uint2 Am  = sm_w[ai - 64];   // (a01, a11)
            uint2 A4  = sm_w[ai + 4];    // (a02, a12)
            uint2 A4m = sm_w[ai - 60];   // (a03, a13)
#pragma unroll
            for (int t = 0; t < EM_NT; t++) {
                uint32_t bb0 = xw[bi + t * 128];
                uint32_t bb1 = xw[bi + t * 128 + 4];
                mma_tf32(acc[t][0][0], acc[t][0][1], acc[t][0][2], acc[t][0][3],
                         A.x, Am.x, A4.x, A4m.x, bb0, bb1);
                mma_tf32(acc[t][1][0], acc[t][1][1], acc[t][1][2], acc[t][1][3],
                         A.y, Am.y, A4.y, A4m.y, bb0, bb1);
            }
            ai += 8; bi += 8;
        }
    }

    // epilogue: raw partial sums to padded buffer (indices < PSTR, no guard)
    float* pz = g_p[z];
#pragma unroll
    for (int t = 0; t < EM_NT; t++) {
        int base = LOc + wrel + t * 128;
        int p0   = base + 8 * grp + 2 * tig;
        int p2   = p0 + 64;
#pragma unroll
        for (int oc = 0; oc < 2; oc++) {
            float* op = pz + (size_t)(b * 2 + oc) * PSTR;
            *(float2*)&op[p0] = make_float2(acc[t][oc][0], acc[t][oc][1]);
            *(float2*)&op[p2] = make_float2(acc[t][oc][2], acc[t][oc][3]);
        }
    }
}

// ---------------------------------------------------------------------------
// Kernel 4b: combine partial halves + sigmoid + store sliced output
// ---------------------------------------------------------------------------
__global__ __launch_bounds__(256)
void effect_combine(float* __restrict__ out)
{
    const int b  = blockIdx.y;
    const int oc = blockIdx.z;
    const int l  = (blockIdx.x * 256 + threadIdx.x) * 4;
    if (l >= LOUT) return;

    const float* p0 = g_p[0] + (size_t)(b * 2 + oc) * PSTR;
    const float* p1 = g_p[1] + (size_t)(b * 2 + oc) * PSTR;
    float4 a = *(const float4*)&p0[l];
    float4 c = *(const float4*)&p1[l];
    float4 r;
    r.x = 1.f / (1.f + __expf(-(a.x + c.x)));
    r.y = 1.f / (1.f + __expf(-(a.y + c.y)));
    r.z = 1.f / (1.f + __expf(-(a.z + c.z)));
    r.w = 1.f / (1.f + __expf(-(a.w + c.w)));
    *(float4*)&out[(size_t)(b * 2 + oc) * LOUT + l] = r;
}

// ---------------------------------------------------------------------------
// Launch
// ---------------------------------------------------------------------------
extern "C" void kernel_launch(void* const* d_in, const int* in_sizes, int n_in,
                              void* d_out, int out_size)
{
    const float* x   = (const float*)d_in[0];
    const float* wm  = (const float*)d_in[1];
    const float* bm  = (const float*)d_in[2];
    const float* wr  = (const float*)d_in[3];
    const float* br  = (const float*)d_in[4];
    const float* wf  = (const float*)d_in[5];
    const float* bf  = (const float*)d_in[6];
    const float* wex = (const float*)d_in[7];
    const float* bex = (const float*)d_in[8];
    const float* wef = (const float*)d_in[9];
    const float* bef = (const float*)d_in[10];
    float* out = (float*)d_out;

    motif_kernel  <<<dim3(L / MT_POS, B), MT_TH>>>(x, wm, bm, wr, br);
    fftconv_kernel<<<dim3(L / FT_POS, B), FT_TH>>>(wf, bf);
    gate_kernel   <<<dim3(L / 2048, B), 256>>>(wex, bex);
    effect_main   <<<dim3((LOUT + EM_POS - 1) / EM_POS, B, 2), EM_TH>>>(wef, bef);
    effect_combine<<<dim3((LOUT / 4 + 255) / 256, B, 2), 256>>>(out);
}

// round 17
// speedup vs baseline: 1.6740x; 1.1585x over previous
#include <cuda_runtime.h>
#include <cuda_fp16.h>
#include <math.h>
#include <stdint.h>

// ---------------------------------------------------------------------------
// Shapes (fixed by the problem)
// ---------------------------------------------------------------------------
#define B    32
#define L    65536
#define LOUT 64536          // L - 1000 (slice [500:-500])
#define PSTR 65536          // padded stride for effect partial buffers

// Scratch (device globals; allocation in kernel_launch is forbidden)
__device__ float g_y[(size_t)B * 40 * L];   // motif output (post-softplus)
__device__ float g_s[(size_t)B * 4 * L];    // reduce output
__device__ float g_t[(size_t)B * 4 * L];    // fftconv output
__device__ float g_m[(size_t)B * 40 * L];   // motifact (gated)
__device__ float g_p[2][(size_t)B * 2 * PSTR]; // effect partial sums (ch halves)

// ---------------------------------------------------------------------------
// MMA helpers
// ---------------------------------------------------------------------------
__device__ __forceinline__ uint32_t f2tf(float v) {
    uint32_t r;
    asm("cvt.rna.tf32.f32 %0, %1;" : "=r"(r) : "f"(v));
    return r;
}

__device__ __forceinline__ void mma_tf32(float& d0, float& d1, float& d2, float& d3,
                                         uint32_t a0, uint32_t a1, uint32_t a2, uint32_t a3,
                                         uint32_t b0, uint32_t b1) {
    asm volatile(
        "mma.sync.aligned.m16n8k8.row.col.f32.tf32.tf32.f32 "
        "{%0,%1,%2,%3}, {%4,%5,%6,%7}, {%8,%9}, {%0,%1,%2,%3};\n"
        : "+f"(d0), "+f"(d1), "+f"(d2), "+f"(d3)
        : "r"(a0), "r"(a1), "r"(a2), "r"(a3), "r"(b0), "r"(b1));
}

__device__ __forceinline__ void mma_f16(float& d0, float& d1, float& d2, float& d3,
                                        uint32_t a0, uint32_t a1, uint32_t a2, uint32_t a3,
                                        uint32_t b0, uint32_t b1) {
    asm volatile(
        "mma.sync.aligned.m16n8k16.row.col.f32.f16.f16.f32 "
        "{%0,%1,%2,%3}, {%4,%5,%6,%7}, {%8,%9}, {%0,%1,%2,%3};\n"
        : "+f"(d0), "+f"(d1), "+f"(d2), "+f"(d3)
        : "r"(a0), "r"(a1), "r"(a2), "r"(a3), "r"(b0), "r"(b1));
}

__device__ __forceinline__ float softplusf(float v) {
    return fmaxf(v, 0.f) + __logf(1.f + __expf(-fabsf(v)));
}

// ---------------------------------------------------------------------------
// Kernel 1: motif conv (4->40, K=51, pad 25) + softplus + FUSED reduce (40->4)
//   (R14/R16 measured — frozen)
// ---------------------------------------------------------------------------
#define MT_POS 512
#define MT_TH  256
#define MT_NT  8
#define MT_KS  60
#define MT_WN  (24 * MT_KS)
#define MT_XW  576

__global__ __launch_bounds__(MT_TH)
void motif_kernel(const float* __restrict__ x,
                  const float* __restrict__ wm, const float* __restrict__ bm,
                  const float* __restrict__ wr, const float* __restrict__ br)
{
    __shared__ __align__(16) uint2 swt[MT_WN];
    __shared__ __align__(16) uint2 sxw[MT_XW];
    __shared__ float srw[160];
    __shared__ float srb[4];

    const int b    = blockIdx.y;
    const int LOc  = blockIdx.x * MT_POS;
    const int tid  = threadIdx.x;
    const int wid  = tid >> 5;
    const int lane = tid & 31;
    const int grp  = lane >> 2;
    const int tig  = lane & 3;
    const int wrel = wid * (MT_NT * 8);

    if (tid < 160) srw[tid] = wr[tid];
    if (tid < 4)   srb[tid] = br[tid];

    float acc[MT_NT][3][4];
#pragma unroll
    for (int m = 0; m < 3; m++) {
        int oca = m * 16 + grp;
        int ocb = oca + 8;
        float ba = bm[oca];
        float bb = (ocb < 40) ? bm[ocb] : 0.f;
#pragma unroll
        for (int t = 0; t < MT_NT; t++) {
            acc[t][m][0] = ba; acc[t][m][1] = ba;
            acc[t][m][2] = bb; acc[t][m][3] = bb;
        }
    }

#pragma unroll 1
    for (int c = 0; c < 4; c++) {
        __syncthreads();
        for (int i = tid; i < MT_WN; i += MT_TH) {
            int mg = i / MT_KS;
            int j  = i - mg * MT_KS;
            int m  = mg >> 3, g = mg & 7;
            int oca = m * 16 + g, ocb = oca + 8;
            float va = 0.f, vb = 0.f;
            if (j < 51) {
                va = wm[(oca * 4 + c) * 51 + j];
                if (ocb < 40) vb = wm[(ocb * 4 + c) * 51 + j];
            }
            swt[i] = make_uint2(f2tf(va), f2tf(vb));
        }
        {
            const float* xc = &x[(size_t)(b * 4 + c) * L];
            for (int i = tid; i < MT_XW; i += MT_TH) {
                int g0 = LOc - 25 + i;
                int g4 = g0 + 4;
                float v0 = (g0 >= 0 && g0 < L) ? xc[g0] : 0.f;
                float v1 = (g4 >= 0 && g4 < L) ? xc[g4] : 0.f;
                sxw[i] = make_uint2(f2tf(v0), f2tf(v1));
            }
        }
        __syncthreads();

#pragma unroll 1
        for (int kc = 0; kc < 7; kc++) {
            uint2 aP[3], aQ[3];
#pragma unroll
            for (int m = 0; m < 3; m++) {
                int base = (m * 8 + grp) * MT_KS + kc * 8 + tig;
                aP[m] = swt[base];
                aQ[m] = swt[base + 4];
            }
            int bi = wrel + grp + tig + kc * 8;
#pragma unroll
            for (int t = 0; t < MT_NT; t++) {
                uint2 bb = sxw[bi + t * 8];
#pragma unroll
                for (int m = 0; m < 3; m++)
                    mma_tf32(acc[t][m][0], acc[t][m][1], acc[t][m][2], acc[t][m][3],
                             aP[m].x, aP[m].y, aQ[m].x, aQ[m].y, bb.x, bb.y);
            }
        }
    }

#pragma unroll 1
    for (int t = 0; t < MT_NT; t++) {
        int p0 = LOc + wrel + t * 8 + 2 * tig;
        float part[4][2];
#pragma unroll
        for (int rc = 0; rc < 4; rc++) { part[rc][0] = 0.f; part[rc][1] = 0.f; }

#pragma unroll
        for (int m = 0; m < 3; m++) {
            int oca = m * 16 + grp;
            float ya0 = softplusf(acc[t][m][0]);
            float ya1 = softplusf(acc[t][m][1]);
            *(float2*)&g_y[(size_t)(b * 40 + oca) * L + p0] = make_float2(ya0, ya1);
#pragma unroll
            for (int rc = 0; rc < 4; rc++) {
                float wv = srw[rc * 40 + oca];
                part[rc][0] = fmaf(wv, ya0, part[rc][0]);
                part[rc][1] = fmaf(wv, ya1, part[rc][1]);
            }
            if (m < 2) {
                int ocb = oca + 8;
                float yb0 = softplusf(acc[t][m][2]);
                float yb1 = softplusf(acc[t][m][3]);
                *(float2*)&g_y[(size_t)(b * 40 + ocb) * L + p0] = make_float2(yb0, yb1);
#pragma unroll
                for (int rc = 0; rc < 4; rc++) {
                    float wv = srw[rc * 40 + ocb];
                    part[rc][0] = fmaf(wv, yb0, part[rc][0]);
                    part[rc][1] = fmaf(wv, yb1, part[rc][1]);
                }
            }
        }
#pragma unroll
        for (int mask = 4; mask <= 16; mask <<= 1) {
#pragma unroll
            for (int rc = 0; rc < 4; rc++) {
                part[rc][0] += __shfl_xor_sync(0xffffffffu, part[rc][0], mask);
                part[rc][1] += __shfl_xor_sync(0xffffffffu, part[rc][1], mask);
            }
        }
        if (grp == 0) {
#pragma unroll
            for (int rc = 0; rc < 4; rc++) {
                float2 sv = make_float2(part[rc][0] + srb[rc], part[rc][1] + srb[rc]);
                *(float2*)&g_s[(size_t)(b * 4 + rc) * L + p0] = sv;
            }
        }
    }
}

// ---------------------------------------------------------------------------
// Kernel 2: fftconv (4->4, K=401, pad 200) via tf32 mma  (R10 proven — frozen)
// ---------------------------------------------------------------------------
#define FT_POS   1024
#define FT_TH    128
#define FT_NT    8
#define FT_NJ    432
#define FT_WOFF  24
#define FT_WPAD  464
#define FT_XW    1472

__global__ __launch_bounds__(FT_TH)
void fftconv_kernel(const float* __restrict__ wf, const float* __restrict__ bf)
{
    __shared__ __align__(16) uint2 sx[FT_XW];
    __shared__ __align__(16) uint2 sw[4 * FT_WPAD];

    const int b    = blockIdx.y;
    const int TO0  = blockIdx.x * FT_POS;
    const int tid  = threadIdx.x;
    const int wid  = tid >> 5;
    const int lane = tid & 31;
    const int grp  = lane >> 2;
    const int tig  = lane & 3;
    const int wrel = wid * (FT_NT * 32);

    const int oc_lo = grp >> 2;
    const int oc_hi = oc_lo + 2;
    const int mp    = grp & 3;

    float acc[FT_NT][4];
    {
        float blo = bf[oc_lo], bhi = bf[oc_hi];
#pragma unroll
        for (int t = 0; t < FT_NT; t++) {
            acc[t][0] = blo; acc[t][1] = blo;
            acc[t][2] = bhi; acc[t][3] = bhi;
        }
    }

#pragma unroll 1
    for (int c = 0; c < 4; c++) {
        __syncthreads();
        for (int i = tid; i < 4 * FT_WPAD; i += FT_TH) {
            int oc = i / FT_WPAD;
            int r  = i - oc * FT_WPAD;
            int k0 = r - FT_WOFF;
            int k1 = k0 + 4;
            float v0 = (k0 >= 0 && k0 < 401) ? wf[(oc * 4 + c) * 401 + k0] : 0.f;
            float v1 = (k1 >= 0 && k1 < 401) ? wf[(oc * 4 + c) * 401 + k1] : 0.f;
            sw[i] = make_uint2(f2tf(v0), f2tf(v1));
        }
        {
            const float* sp = &g_s[(size_t)(b * 4 + c) * L];
            for (int i = tid; i < FT_XW; i += FT_TH) {
                int g  = TO0 - 200 + i;
                int g4 = g + 4;
                float v0 = (g  >= 0 && g  < L) ? sp[g]  : 0.f;
                float v1 = (g4 >= 0 && g4 < L) ? sp[g4] : 0.f;
                sx[i] = make_uint2(f2tf(v0), f2tf(v1));
            }
        }
        __syncthreads();

        const uint2* xw  = &sx[wrel];
        const uint2* wlo = &sw[oc_lo * FT_WPAD];
        const uint2* whi = &sw[oc_hi * FT_WPAD];
        int ai = FT_WOFF + tig - 8 * mp;
        int bi = grp + tig;
#pragma unroll 1
        for (int J0 = 0; J0 < FT_NJ; J0 += 8) {
            uint2 aLo = wlo[ai];
            uint2 aHi = whi[ai];
#pragma unroll
            for (int t = 0; t < FT_NT; t++) {
                uint2 bb = xw[bi + t * 32];
                mma_tf32(acc[t][0], acc[t][1], acc[t][2], acc[t][3],
                         aLo.x, aHi.x, aLo.y, aHi.y, bb.x, bb.y);
            }
            ai += 8; bi += 8;
        }
    }

    float* tlo = &g_t[(size_t)(b * 4 + oc_lo) * L];
    float* thi = &g_t[(size_t)(b * 4 + oc_hi) * L];
#pragma unroll
    for (int t = 0; t < FT_NT; t++) {
        int pos = TO0 + wrel + t * 32 + 8 * mp + 2 * tig;
        *(float2*)&tlo[pos] = make_float2(acc[t][0], acc[t][1]);
        *(float2*)&thi[pos] = make_float2(acc[t][2], acc[t][3]);
    }
}

// ---------------------------------------------------------------------------
// Kernel 3: expand (4->40, 1x1) + sigmoid gate * y -> motifact (R14 — frozen)
// ---------------------------------------------------------------------------
__global__ __launch_bounds__(256)
void gate_kernel(const float* __restrict__ we, const float* __restrict__ be)
{
    __shared__ float sw[160];
    __shared__ float sb[40];
    const int tid = threadIdx.x;
    if (tid < 160) sw[tid] = we[tid];
    if (tid < 40)  sb[tid] = be[tid];
    __syncthreads();

    const int b = blockIdx.y;
    const int l = (blockIdx.x * 256 + tid) * 8;

    float4 tv[4][2];
#pragma unroll
    for (int rc = 0; rc < 4; rc++) {
        tv[rc][0] = *(const float4*)&g_t[(size_t)(b * 4 + rc) * L + l];
        tv[rc][1] = *(const float4*)&g_t[(size_t)(b * 4 + rc) * L + l + 4];
    }

    for (int oc = 0; oc < 40; oc++) {
        float w0 = sw[oc * 4 + 0], w1 = sw[oc * 4 + 1];
        float w2 = sw[oc * 4 + 2], w3 = sw[oc * 4 + 3];
        float bb = sb[oc];
        size_t idx = (size_t)(b * 40 + oc) * L + l;
#pragma unroll
        for (int h = 0; h < 2; h++) {
            float4 g;
            g.x = bb + w0 * tv[0][h].x + w1 * tv[1][h].x + w2 * tv[2][h].x + w3 * tv[3][h].x;
            g.y = bb + w0 * tv[0][h].y + w1 * tv[1][h].y + w2 * tv[2][h].y + w3 * tv[3][h].y;
            g.z = bb + w0 * tv[0][h].z + w1 * tv[1][h].z + w2 * tv[2][h].z + w3 * tv[3][h].z;
            g.w = bb + w0 * tv[0][h].w + w1 * tv[1][h].w + w2 * tv[2][h].w + w3 * tv[3][h].w;
            g.x = 1.f / (1.f + __expf(-g.x));
            g.y = 1.f / (1.f + __expf(-g.y));
            g.z = 1.f / (1.f + __expf(-g.z));
            g.w = 1.f / (1.f + __expf(-g.w));
            float4 yv = *(const float4*)&g_y[idx + h * 4];
            float4 mv = make_float4(g.x * yv.x, g.y * yv.y, g.z * yv.z, g.w * yv.w);
            *(float4*)&g_m[idx + h * 4] = mv;
        }
    }
}

// ---------------------------------------------------------------------------
// Kernel 4: effect conv (40->2, K=601) via fp16 m16n8k16 mma (fp32 accum).
//   fp16 mantissa (10 bits) == tf32 mantissa, so precision is unchanged;
//   K doubles 8 -> 16, halving MMA count and smem wavefronts per MAC.
//   A: per-oc half array, band at offset 128; frag = 4 aligned LDS.32
//     (ai = 128 + 2tig - 8grp + J0 is always even).
//   B: duplicated-pair window sx2[i] = {x[i], x[i+1]} -> 1 LDS.32 per reg
//     at any parity.
//   NT=8 tiles x 128 pos = 1024 pos/warp; CTA 4096 pos; z-split 2 x 20 ch.
// ---------------------------------------------------------------------------
#define EM_POS   4096       // positions per CTA
#define EM_TH    128
#define EM_NT    8          // 128-pos tiles per warp
#define EM_WLEN  4704       // uint32 {x[i], x[i+1]} window entries
#define EM_WPADH 864        // halves per oc weight band (offset 128 + 601 + pad)
#define EM_NJ    736        // extended j range (46 chunks of 16)

__global__ __launch_bounds__(EM_TH)
void effect_main(const float* __restrict__ w, const float* __restrict__ bias)
{
    __shared__ __align__(16) uint32_t sm_x[EM_WLEN];       // {h(x[i]), h(x[i+1])}
    __shared__ __align__(16) __half sm_wh[2 * EM_WPADH];   // [oc][band halves]

    const int b    = blockIdx.y;
    const int z    = blockIdx.z;                    // channel half
    const int LOc  = blockIdx.x * EM_POS;
    const int tid  = threadIdx.x;
    const int wid  = tid >> 5;
    const int lane = tid & 31;
    const int grp  = lane >> 2;
    const int tig  = lane & 3;
    const int wrel = wid * (EM_NT * 128);           // 1024 positions per warp

    float acc[EM_NT][2][4];
    const float b0v = (z == 0) ? bias[0] : 0.f;
    const float b1v = (z == 0) ? bias[1] : 0.f;
#pragma unroll
    for (int t = 0; t < EM_NT; t++)
#pragma unroll
        for (int r = 0; r < 4; r++) { acc[t][0][r] = b0v; acc[t][1][r] = b1v; }

#pragma unroll 1
    for (int ch = 0; ch < 20; ch++) {
        const int chg = z * 20 + ch;
        __syncthreads();
        // weights: band at offset 128 (halves), per-oc arrays, zero-guarded
        for (int i = tid; i < 2 * EM_WPADH; i += EM_TH) {
            int oc = i / EM_WPADH;
            int k  = (i - oc * EM_WPADH) - 128;
            float v = (k >= 0 && k < 601)
                      ? w[((size_t)(oc * 40 + chg)) * 601 + k] : 0.f;
            sm_wh[i] = __float2half_rn(v);
        }
        // x window: duplicated pairs {h(x[g]), h(x[g+1])}
        {
            const float* xm = &g_m[(size_t)(b * 40 + chg) * L];
            for (int i = tid; i < EM_WLEN; i += EM_TH) {
                int g = LOc + 200 + i;
                float v0 = (g < L)     ? xm[g]     : 0.f;
                float v1 = (g + 1 < L) ? xm[g + 1] : 0.f;
                __half2 hv = __floats2half2_rn(v0, v1);
                sm_x[i] = *(uint32_t*)&hv;
            }
        }
        __syncthreads();

        const uint32_t* xw = &sm_x[wrel];
        const __half* w0h = &sm_wh[0];
        const __half* w1h = &sm_wh[EM_WPADH];
        int ai = 128 + 2 * tig - 8 * grp;   // half index; even; + J0 each step
        int bi = grp + 2 * tig;             // pair index; + J0 each step (+ t*128)
#pragma unroll 1
        for (int J0 = 0; J0 < EM_NJ; J0 += 16) {
            uint32_t a00 = *(const uint32_t*)&w0h[ai];        // (g,   2tig..+1)
            uint32_t a01 = *(const uint32_t*)&w0h[ai - 64];   // (g+8, ...)
            uint32_t a02 = *(const uint32_t*)&w0h[ai + 8];    // (g,   2tig+8..)
            uint32_t a03 = *(const uint32_t*)&w0h[ai - 56];   // (g+8, +8)
            uint32_t a10 = *(const uint32_t*)&w1h[ai];
            uint32_t a11 = *(const uint32_t*)&w1h[ai - 64];
            uint32_t a12 = *(const uint32_t*)&w1h[ai + 8];
            uint32_t a13 = *(const uint32_t*)&w1h[ai - 56];
#pragma unroll
            for (int t = 0; t < EM_NT; t++) {
                uint32_t bb0 = xw[bi + t * 128];       // rows 2tig..+1, col g
                uint32_t bb1 = xw[bi + t * 128 + 8];   // rows +8
                mma_f16(acc[t][0][0], acc[t][0][1], acc[t][0][2], acc[t][0][3],
                        a00, a01, a02, a03, bb0, bb1);
                mma_f16(acc[t][1][0], acc[t][1][1], acc[t][1][2], acc[t][1][3],
                        a10, a11, a12, a13, bb0, bb1);
            }
            ai += 16; bi += 16;
        }
    }

    // epilogue: raw partial sums to padded buffer (indices < PSTR, no guard)
    float* pz = g_p[z];
#pragma unroll
    for (int t = 0; t < EM_NT; t++) {
        int base = LOc + wrel + t * 128;
        int p0   = base + 8 * grp + 2 * tig;
        int p2   = p0 + 64;
#pragma unroll
        for (int oc = 0; oc < 2; oc++) {
            float* op = pz + (size_t)(b * 2 + oc) * PSTR;
            *(float2*)&op[p0] = make_float2(acc[t][oc][0], acc[t][oc][1]);
            *(float2*)&op[p2] = make_float2(acc[t][oc][2], acc[t][oc][3]);
        }
    }
}

// ---------------------------------------------------------------------------
// Kernel 4b: combine partial halves + sigmoid + store sliced output
// ---------------------------------------------------------------------------
__global__ __launch_bounds__(256)
void effect_combine(float* __restrict__ out)
{
    const int b  = blockIdx.y;
    const int oc = blockIdx.z;
    const int l  = (blockIdx.x * 256 + threadIdx.x) * 4;
    if (l >= LOUT) return;

    const float* p0 = g_p[0] + (size_t)(b * 2 + oc) * PSTR;
    const float* p1 = g_p[1] + (size_t)(b * 2 + oc) * PSTR;
    float4 a = *(const float4*)&p0[l];
    float4 c = *(const float4*)&p1[l];
    float4 r;
    r.x = 1.f / (1.f + __expf(-(a.x + c.x)));
    r.y = 1.f / (1.f + __expf(-(a.y + c.y)));
    r.z = 1.f / (1.f + __expf(-(a.z + c.z)));
    r.w = 1.f / (1.f + __expf(-(a.w + c.w)));
    *(float4*)&out[(size_t)(b * 2 + oc) * LOUT + l] = r;
}

// ---------------------------------------------------------------------------
// Launch
// ---------------------------------------------------------------------------
extern "C" void kernel_launch(void* const* d_in, const int* in_sizes, int n_in,
                              void* d_out, int out_size)
{
    const float* x   = (const float*)d_in[0];
    const float* wm  = (const float*)d_in[1];
    const float* bm  = (const float*)d_in[2];
    const float* wr  = (const float*)d_in[3];
    const float* br  = (const float*)d_in[4];
    const float* wf  = (const float*)d_in[5];
    const float* bf  = (const float*)d_in[6];
    const float* wex = (const float*)d_in[7];
    const float* bex = (const float*)d_in[8];
    const float* wef = (const float*)d_in[9];
    const float* bef = (const float*)d_in[10];
    float* out = (float*)d_out;

    motif_kernel  <<<dim3(L / MT_POS, B), MT_TH>>>(x, wm, bm, wr, br);
    fftconv_kernel<<<dim3(L / FT_POS, B), FT_TH>>>(wf, bf);
    gate_kernel   <<<dim3(L / 2048, B), 256>>>(wex, bex);
    effect_main   <<<dim3((LOUT + EM_POS - 1) / EM_POS, B, 2), EM_TH>>>(wef, bef);
    effect_combine<<<dim3((LOUT / 4 + 255) / 256, B, 2), 256>>>(out);
}